// round 5
// baseline (speedup 1.0000x reference)
#include <cuda_runtime.h>

#define E_EDGES 65536
#define NGO 4096
#define B_SZ 16
#define G_SZ 1024

// ---------------- scratch (__device__ globals; no allocs allowed) ----------------
__device__ float g_xcat[B_SZ * G_SZ];        // [B][G]  (pre-lrelu, bias-initialized)
__device__ float g_h[NGO * 96];              // [N][B][6]
__device__ float g_hn[NGO * 128];            // [N][B][2][4]
__device__ float g_si[NGO * 32];             // [N][B][2]
__device__ float g_sj[NGO * 32];             // [N][B][2]
__device__ float g_o[B_SZ * 16384];          // [B][C*N]  (lrelu applied)
__device__ int   g_cnt[NGO];                 // zero-init; k_scan re-zeroes each call
__device__ int   g_off[NGO + 1];
__device__ int   g_cur[NGO];
__device__ int   g_csr[E_EDGES];             // src per CSR slot
__device__ int   g_eflag;                    // 1 = edge_index is int64

__device__ __forceinline__ float lrelu(float x, float s) { return x >= 0.f ? x : s * x; }

// f32x2 packed math (Blackwell FFMA2, PTX-only)
__device__ __forceinline__ void fma2(unsigned long long& d, unsigned long long a, unsigned long long b) {
    asm("fma.rn.f32x2 %0, %1, %2, %0;" : "+l"(d) : "l"(a), "l"(b));
}
__device__ __forceinline__ unsigned long long mul2(unsigned long long a, unsigned long long b) {
    unsigned long long d; asm("mul.rn.f32x2 %0, %1, %2;" : "=l"(d) : "l"(a), "l"(b)); return d;
}
__device__ __forceinline__ float sum2(unsigned long long v) {
    return __uint_as_float((unsigned)v) + __uint_as_float((unsigned)(v >> 32));
}

// ---------------- L1: fused init (edge dtype detect + xcat=bias) ----------------
__global__ void k_init(const int* __restrict__ ei, const float* __restrict__ bsub) {
    int bid = blockIdx.x, tid = threadIdx.x;
    if (bid < 64) {
        int i = bid * 256 + tid;                 // 0..16383 = b*1024+g
        g_xcat[i] = bsub[i & 1023];
    } else {
        // int64 little-endian with values < 4096 -> every odd 32-bit word is 0.
        int ok = (ei[2 * tid + 1] == 0);
        int all = __syncthreads_and(ok);
        if (tid == 0) g_eflag = all;
    }
}
__device__ __forceinline__ int eidx(const int* __restrict__ p, int i) {
    return g_eflag ? p[2 * i] : p[i];
}

// ---------------- L2: per-gene subnet. block = 4 genes x 64 t x 8 b ----------------
__global__ __launch_bounds__(256) void k_subnet(const float* __restrict__ x,
                                                const float* __restrict__ Wsub) {
    int g0 = blockIdx.x * 4;
    int tid = threadIdx.x;
    int c = tid & 15, tr = tid >> 4;             // c: 16 consecutive float4 cols (256B)
    int gene = g0 + (c >> 2), pq = c & 3;
    int b0 = blockIdx.z * 8;
    const float4* x4 = (const float4*)x;
    const float4* w4 = (const float4*)Wsub;
    float acc[8];
#pragma unroll
    for (int b = 0; b < 8; b++) acc[b] = 0.f;
    int tbase = blockIdx.y * 64;
#pragma unroll 1
    for (int pass = 0; pass < 4; pass++) {
        int t = tbase + pass * 16 + tr;
        float4 w = w4[gene * 1024 + t * 4 + pq];
        int xoff = t * 4096 + g0 * 4 + c;
#pragma unroll
        for (int b = 0; b < 8; b++) {
            float4 xv = x4[(b0 + b) * 1048576 + xoff];
            acc[b] += w.x * xv.x + w.y * xv.y + w.z * xv.z + w.w * xv.w;
        }
    }
    __shared__ float red[8][4][8];
    int lane = tid & 31, wid = tid >> 5;
#pragma unroll
    for (int b = 0; b < 8; b++) {
        float v = acc[b];
        v += __shfl_xor_sync(0xffffffffu, v, 16);
        v += __shfl_xor_sync(0xffffffffu, v, 2);
        v += __shfl_xor_sync(0xffffffffu, v, 1);
        if ((lane & 3) == 0 && lane < 16) red[wid][lane >> 2][b] = v;
    }
    __syncthreads();
    if (tid < 32) {
        int gl = tid >> 3, b = tid & 7;
        float s = 0.f;
#pragma unroll
        for (int w2 = 0; w2 < 8; w2++) s += red[w2][gl][b];
        atomicAdd(&g_xcat[(b0 + b) * G_SZ + g0 + gl], s);
    }
}

// ---------------- L3: histogram of destinations ----------------
__global__ void k_hist(const int* __restrict__ ei) {
    int e = blockIdx.x * 256 + threadIdx.x;
    int dst = eidx(ei, E_EDGES + e);
    atomicAdd(&g_cnt[dst], 1);
}

// ---------------- L4 (PROFILED): masked FC. warp = 3 rows, 8 warps/block ----------------
__global__ __launch_bounds__(256, 3) void k_fc(const float* __restrict__ fw,
                                               const float* __restrict__ mr,
                                               const float* __restrict__ fb) {
    extern __shared__ float xs[];                 // x_cat [16][1024] (lrelu applied)
    int tid = threadIdx.x;
    {
        const float4* src4 = (const float4*)g_xcat;
        float4* xs4 = (float4*)xs;
        for (int q = tid; q < 4096; q += 256) {
            float4 v = src4[q];
            v.x = lrelu(v.x, 0.01f); v.y = lrelu(v.y, 0.01f);
            v.z = lrelu(v.z, 0.01f); v.w = lrelu(v.w, 0.01f);
            xs4[q] = v;
        }
    }
    __syncthreads();
    int wid = tid >> 5, lane = tid & 31;
    int grp = blockIdx.x * 8 + wid;               // 0..8191, 3 rows each
    int j0 = grp * 3;
    int bg = lane >> 3, sub = lane & 7;
    const ulonglong2* mrow = (const ulonglong2*)(mr + (size_t)j0 * 1024);
    const ulonglong2* wrow = (const ulonglong2*)(fw + (size_t)j0 * 1024);
    const ulonglong2* xsu = (const ulonglong2*)xs;

    unsigned long long acc[3][4];
#pragma unroll
    for (int r = 0; r < 3; r++)
#pragma unroll
        for (int b = 0; b < 4; b++) acc[r][b] = 0ull;

#pragma unroll 4
    for (int it = 0; it < 32; it++) {
        int q = it * 8 + sub;                     // quad index 0..255 (128B per 8-lane group)
        ulonglong2 m = mrow[q];
        unsigned long long p0[3], p1[3];
#pragma unroll
        for (int r = 0; r < 3; r++) {
            ulonglong2 w = wrow[r * 256 + q];
            p0[r] = mul2(w.x, m.x);
            p1[r] = mul2(w.y, m.y);
        }
#pragma unroll
        for (int b = 0; b < 4; b++) {
            ulonglong2 xv = xsu[(bg * 4 + b) * 256 + q];
#pragma unroll
            for (int r = 0; r < 3; r++) {
                fma2(acc[r][b], p0[r], xv.x);
                fma2(acc[r][b], p1[r], xv.y);
            }
        }
    }
#pragma unroll
    for (int r = 0; r < 3; r++) {
#pragma unroll
        for (int b = 0; b < 4; b++) {
            float v = sum2(acc[r][b]);
            v += __shfl_xor_sync(0xffffffffu, v, 4, 8);
            v += __shfl_xor_sync(0xffffffffu, v, 2, 8);
            v += __shfl_xor_sync(0xffffffffu, v, 1, 8);
            if (sub == 0) {
                int j = j0 + r;
                int d = j >> 12, n = j & 4095;
                v += fb[j];
                g_h[n * 96 + (bg * 4 + b) * 6 + d] = lrelu(v, 0.01f);
            }
        }
    }
}

// ---------------- L5: scan (+ re-zero cnt for next replay, + out bias init) ----------------
__global__ void k_scan(float* __restrict__ out, const float* __restrict__ ob) {
    int lane = threadIdx.x;
    int base = lane * 128;
    int s = 0;
    for (int i = 0; i < 128; i++) s += g_cnt[base + i];
    int v = s;
#pragma unroll
    for (int d = 1; d < 32; d <<= 1) {
        int o = __shfl_up_sync(0xffffffffu, v, d);
        if (lane >= d) v += o;
    }
    int run = v - s;                              // exclusive
    for (int i = 0; i < 128; i++) {
        int c = g_cnt[base + i];
        g_off[base + i] = run;
        g_cur[base + i] = run;
        g_cnt[base + i] = 0;                      // ready for next replay
        run += c;
    }
    if (lane == 31) g_off[NGO] = run;
    for (int i = lane; i < 512; i += 32) out[i] = ob[i & 31];
}

// ---------------- L6: fused GAT projection + CSR scatter ----------------
__global__ void k_mid(const float* __restrict__ gw, const float* __restrict__ gatt,
                      const int* __restrict__ ei) {
    int tid = threadIdx.x;
    if (blockIdx.x < 256) {
        __shared__ float sgw[48], satt[16];
        if (tid < 48) sgw[tid] = gw[tid];
        if (tid < 16) satt[tid] = gatt[tid];
        __syncthreads();
        int gid = blockIdx.x * 256 + tid;         // n*16 + b
        const float2* hp = (const float2*)(g_h + gid * 6);
        float2 h01 = hp[0], h23 = hp[1], h45 = hp[2];
        float h6[6] = {h01.x, h01.y, h23.x, h23.y, h45.x, h45.y};
        float hn8[8];
#pragma unroll
        for (int k = 0; k < 8; k++) {
            float s = 0.f;
#pragma unroll
            for (int d = 0; d < 6; d++) s += h6[d] * sgw[d * 8 + k];
            hn8[k] = s;
        }
        float4* hnp = (float4*)(g_hn + gid * 8);
        hnp[0] = make_float4(hn8[0], hn8[1], hn8[2], hn8[3]);
        hnp[1] = make_float4(hn8[4], hn8[5], hn8[6], hn8[7]);
        float2 si, sj;
        si.x = hn8[0]*satt[0] + hn8[1]*satt[1] + hn8[2]*satt[2] + hn8[3]*satt[3];
        sj.x = hn8[0]*satt[4] + hn8[1]*satt[5] + hn8[2]*satt[6] + hn8[3]*satt[7];
        si.y = hn8[4]*satt[8] + hn8[5]*satt[9] + hn8[6]*satt[10] + hn8[7]*satt[11];
        sj.y = hn8[4]*satt[12] + hn8[5]*satt[13] + hn8[6]*satt[14] + hn8[7]*satt[15];
        ((float2*)g_si)[gid] = si;
        ((float2*)g_sj)[gid] = sj;
    } else {
        int e = (blockIdx.x - 256) * 256 + tid;
        int dst = eidx(ei, E_EDGES + e);
        int src = eidx(ei, e);
        int pos = atomicAdd(&g_cur[dst], 1);
        g_csr[pos] = src;
    }
}

// ---------------- L7: per-destination softmax + aggregate (single pass) ----------------
__global__ __launch_bounds__(128) void k_gat(const float* __restrict__ gbias) {
    int n = blockIdx.x;
    int tid = threadIdx.x;                        // (b,h,c): b=tid>>3, h=(tid>>2)&1, c=tid&3
    __shared__ float s_i_sh[32], s_red[128];
    __shared__ int srcs[128];
    if (tid < 32) s_i_sh[tid] = g_si[n * 32 + tid];
    __syncthreads();
    int base = g_off[n], deg = g_off[n + 1] - base;

    int bh = tid >> 2;
    float acc = 0.f, wsum = 0.f;
    float sib = s_i_sh[bh];
    for (int e0 = 0; e0 < deg; e0 += 128) {
        int m = min(128, deg - e0);
        if (tid < m) srcs[tid] = g_csr[base + e0 + tid];
        __syncthreads();
        for (int i = 0; i < m; i++) {
            int s = srcs[i];
            float a = sib + g_sj[s * 32 + bh];
            a = a >= 0.f ? a : 0.2f * a;
            a = fminf(fmaxf(a, -30.f), 30.f);     // tripwire only; scores are O(1)
            float w = __expf(a);
            wsum += w;
            acc += w * g_hn[s * 128 + tid];
        }
        __syncthreads();
    }
    float r = (wsum > 0.f) ? acc / (wsum * (float)deg) : 0.f;
    s_red[tid] = r;
    __syncthreads();
    if (tid < 64) {
        int b = tid >> 2, c = tid & 3;
        float v = 0.5f * (s_red[b * 8 + c] + s_red[b * 8 + 4 + c]) + gbias[c];
        g_o[b * 16384 + c * 4096 + n] = lrelu(v, 0.01f);
    }
}

// ---------------- L8: readout ----------------
__global__ __launch_bounds__(256) void k_readout(const float* __restrict__ ow, float* __restrict__ out) {
    int k = blockIdx.x, sl = blockIdx.y;
    int tid = threadIdx.x;
    float acc[16];
#pragma unroll
    for (int b = 0; b < 16; b++) acc[b] = 0.f;
    const float* wk = ow + k * 16384 + sl * 4096;
    const float* op = g_o + sl * 4096;
    for (int it = 0; it < 16; it++) {
        int i = tid + it * 256;
        float w = wk[i];
#pragma unroll
        for (int b = 0; b < 16; b++) acc[b] += w * op[b * 16384 + i];
    }
    __shared__ float red[8][16];
    int lane = tid & 31, wid = tid >> 5;
#pragma unroll
    for (int b = 0; b < 16; b++) {
        float v = acc[b];
#pragma unroll
        for (int o = 16; o; o >>= 1) v += __shfl_xor_sync(0xffffffffu, v, o);
        if (lane == 0) red[wid][b] = v;
    }
    __syncthreads();
    if (tid < 16) {
        float s = 0.f;
#pragma unroll
        for (int w = 0; w < 8; w++) s += red[w][tid];
        atomicAdd(&out[tid * 32 + k], s);
    }
}

// ---------------- launch ----------------
extern "C" void kernel_launch(void* const* d_in, const int* in_sizes, int n_in,
                              void* d_out, int out_size) {
    const float* x    = (const float*)d_in[0];
    const int*   ei   = (const int*)  d_in[1];
    const float* Wsub = (const float*)d_in[2];
    const float* bsub = (const float*)d_in[3];
    const float* fw   = (const float*)d_in[4];
    const float* mr   = (const float*)d_in[5];
    const float* fb   = (const float*)d_in[6];
    const float* gw   = (const float*)d_in[7];
    const float* gatt = (const float*)d_in[8];
    const float* gb   = (const float*)d_in[9];
    const float* ow   = (const float*)d_in[10];
    const float* ob   = (const float*)d_in[11];
    float* out = (float*)d_out;

    cudaFuncSetAttribute(k_fc, cudaFuncAttributeMaxDynamicSharedMemorySize, 65536);

    k_init<<<65, 256>>>(ei, bsub);                 // 1
    k_subnet<<<dim3(256, 4, 2), 256>>>(x, Wsub);   // 2
    k_hist<<<256, 256>>>(ei);                      // 3
    k_fc<<<1024, 256, 65536>>>(fw, mr, fb);        // 4  <- profiled launch
    k_scan<<<1, 32>>>(out, ob);                    // 5
    k_mid<<<512, 256>>>(gw, gatt, ei);             // 6
    k_gat<<<4096, 128>>>(gb);                      // 7
    k_readout<<<dim3(32, 4), 256>>>(ow, out);      // 8
}

// round 6
// speedup vs baseline: 1.2538x; 1.2538x over previous
#include <cuda_runtime.h>

#define E_EDGES 65536
#define NGO 4096
#define B_SZ 16
#define G_SZ 1024

// ---------------- scratch (__device__ globals; no allocs allowed) ----------------
__device__ float g_xcat[B_SZ * G_SZ];        // [B][G]  (pre-lrelu, bias-initialized)
__device__ float g_xr[B_SZ * G_SZ];          // lrelu(g_xcat)
__device__ float g_h[NGO * 96];              // [N][B][6]
__device__ float g_hn[NGO * 128];            // [N][B][2][4]
__device__ float g_si[NGO * 32];             // [N][B][2]
__device__ float g_sj[NGO * 32];             // [N][B][2]
__device__ float g_o[B_SZ * 16384];          // [B][C*N]  (lrelu applied)
__device__ int   g_idxcnt[NGO];              // nnz count per mask group
__device__ int   g_idxbuf[NGO * 1024];       // nnz gene indices per mask group
__device__ int   g_cnt[NGO];                 // zero-init; k_scan re-zeroes each call
__device__ int   g_off[NGO + 1];
__device__ int   g_cur[NGO];
__device__ int   g_csr[E_EDGES];             // src per CSR slot
__device__ int   g_eflag;                    // 1 = edge_index is int64

__device__ __forceinline__ float lrelu(float x, float s) { return x >= 0.f ? x : s * x; }

// ---------------- L1: fused init (edge dtype detect + xcat=bias) ----------------
__global__ void k_init(const int* __restrict__ ei, const float* __restrict__ bsub) {
    int bid = blockIdx.x, tid = threadIdx.x;
    if (bid < 64) {
        int i = bid * 256 + tid;                 // 0..16383 = b*1024+g
        g_xcat[i] = bsub[i & 1023];
    } else {
        // int64 little-endian with values < 4096 -> every odd 32-bit word is 0.
        int ok = (ei[2 * tid + 1] == 0);
        int all = __syncthreads_and(ok);
        if (tid == 0) g_eflag = all;
    }
}
__device__ __forceinline__ int eidx(const int* __restrict__ p, int i) {
    return g_eflag ? p[2 * i] : p[i];
}

// ---------------- L2: per-gene subnet. block = 4 genes x 64 t x 8 b ----------------
__global__ __launch_bounds__(256) void k_subnet(const float* __restrict__ x,
                                                const float* __restrict__ Wsub) {
    int g0 = blockIdx.x * 4;
    int tid = threadIdx.x;
    int c = tid & 15, tr = tid >> 4;             // c: 16 consecutive float4 cols (256B)
    int gene = g0 + (c >> 2), pq = c & 3;
    int b0 = blockIdx.z * 8;
    const float4* x4 = (const float4*)x;
    const float4* w4 = (const float4*)Wsub;
    float acc[8];
#pragma unroll
    for (int b = 0; b < 8; b++) acc[b] = 0.f;
    int tbase = blockIdx.y * 64;
#pragma unroll 1
    for (int pass = 0; pass < 4; pass++) {
        int t = tbase + pass * 16 + tr;
        float4 w = w4[gene * 1024 + t * 4 + pq];
        int xoff = t * 4096 + g0 * 4 + c;
#pragma unroll
        for (int b = 0; b < 8; b++) {
            float4 xv = x4[(b0 + b) * 1048576 + xoff];
            acc[b] += w.x * xv.x + w.y * xv.y + w.z * xv.z + w.w * xv.w;
        }
    }
    __shared__ float red[8][4][8];
    int lane = tid & 31, wid = tid >> 5;
#pragma unroll
    for (int b = 0; b < 8; b++) {
        float v = acc[b];
        v += __shfl_xor_sync(0xffffffffu, v, 16);
        v += __shfl_xor_sync(0xffffffffu, v, 2);
        v += __shfl_xor_sync(0xffffffffu, v, 1);
        if ((lane & 3) == 0 && lane < 16) red[wid][lane >> 2][b] = v;
    }
    __syncthreads();
    if (tid < 32) {
        int gl = tid >> 3, b = tid & 7;
        float s = 0.f;
#pragma unroll
        for (int w2 = 0; w2 < 8; w2++) s += red[w2][gl][b];
        atomicAdd(&g_xcat[(b0 + b) * G_SZ + g0 + gl], s);
    }
}

// ---------------- L3: fused prep (mask nnz compaction + dst histogram + lrelu x) ----------------
__global__ void k_pre(const int* __restrict__ ei, const float* __restrict__ mr) {
    int bid = blockIdx.x, tid = threadIdx.x;
    if (bid < 512) {
        // warp per mask group: compact nonzero gene indices of mask row 6*grp
        int grp = bid * 8 + (tid >> 5), lane = tid & 31;
        const float* row = mr + (size_t)grp * 6144;   // rows 6g..6g+5 identical
        int* out = g_idxbuf + grp * 1024;
        int cnt = 0;
#pragma unroll 4
        for (int c = 0; c < 32; c++) {
            float v = row[c * 32 + lane];
            unsigned ball = __ballot_sync(0xffffffffu, v != 0.f);
            if (v != 0.f) out[cnt + __popc(ball & ((1u << lane) - 1u))] = c * 32 + lane;
            cnt += __popc(ball);
        }
        if (lane == 0) g_idxcnt[grp] = cnt;
    } else if (bid < 768) {
        int e = (bid - 512) * 256 + tid;
        int dst = eidx(ei, E_EDGES + e);
        atomicAdd(&g_cnt[dst], 1);
    } else {
        int i = (bid - 768) * 256 + tid;             // 0..16383
        g_xr[i] = lrelu(g_xcat[i], 0.01f);
    }
}

// ---------------- L4 (PROFILED): sparse masked FC. warp = (group, 4 b's) ----------------
__global__ __launch_bounds__(256) void k_fcs(const float* __restrict__ fw,
                                             const float* __restrict__ fb) {
    int tid = threadIdx.x, wid = tid >> 5, lane = tid & 31;
    int grp = blockIdx.x * 2 + (wid >> 2);           // 0..4095
    int b0 = (wid & 3) * 4;                          // 4 b's per warp
    int cnt = g_idxcnt[grp];
    const int* idx = g_idxbuf + grp * 1024;
    const float* wb = fw + (size_t)grp * 6144;
    float acc[6][4];
#pragma unroll
    for (int r = 0; r < 6; r++)
#pragma unroll
        for (int b = 0; b < 4; b++) acc[r][b] = 0.f;

    for (int k0 = 0; k0 < cnt; k0 += 32) {
        int kk = k0 + lane;
        bool on = kk < cnt;
        int g = on ? idx[kk] : 0;
        float xv[4];
#pragma unroll
        for (int b = 0; b < 4; b++) xv[b] = on ? g_xr[(b0 + b) * G_SZ + g] : 0.f;
#pragma unroll
        for (int r = 0; r < 6; r++) {
            float wv = on ? wb[r * 1024 + g] : 0.f;
#pragma unroll
            for (int b = 0; b < 4; b++) acc[r][b] += wv * xv[b];
        }
    }
#pragma unroll
    for (int r = 0; r < 6; r++) {
#pragma unroll
        for (int b = 0; b < 4; b++) {
            float v = acc[r][b];
#pragma unroll
            for (int o = 16; o; o >>= 1) v += __shfl_xor_sync(0xffffffffu, v, o);
            if (lane == 0) {
                int j = grp * 6 + r;
                int d = j >> 12, n = j & 4095;
                g_h[n * 96 + (b0 + b) * 6 + d] = lrelu(v + fb[j], 0.01f);
            }
        }
    }
}

// ---------------- L5: scan (+ re-zero cnt for next replay, + out bias init) ----------------
__global__ void k_scan(float* __restrict__ out, const float* __restrict__ ob) {
    int lane = threadIdx.x;
    int base = lane * 128;
    int s = 0;
    for (int i = 0; i < 128; i++) s += g_cnt[base + i];
    int v = s;
#pragma unroll
    for (int d = 1; d < 32; d <<= 1) {
        int o = __shfl_up_sync(0xffffffffu, v, d);
        if (lane >= d) v += o;
    }
    int run = v - s;                              // exclusive
    for (int i = 0; i < 128; i++) {
        int c = g_cnt[base + i];
        g_off[base + i] = run;
        g_cur[base + i] = run;
        g_cnt[base + i] = 0;                      // ready for next replay
        run += c;
    }
    if (lane == 31) g_off[NGO] = run;
    for (int i = lane; i < 512; i += 32) out[i] = ob[i & 31];
}

// ---------------- L6: fused GAT projection + CSR scatter ----------------
__global__ void k_mid(const float* __restrict__ gw, const float* __restrict__ gatt,
                      const int* __restrict__ ei) {
    int tid = threadIdx.x;
    if (blockIdx.x < 256) {
        __shared__ float sgw[48], satt[16];
        if (tid < 48) sgw[tid] = gw[tid];
        if (tid < 16) satt[tid] = gatt[tid];
        __syncthreads();
        int gid = blockIdx.x * 256 + tid;         // n*16 + b
        const float2* hp = (const float2*)(g_h + gid * 6);
        float2 h01 = hp[0], h23 = hp[1], h45 = hp[2];
        float h6[6] = {h01.x, h01.y, h23.x, h23.y, h45.x, h45.y};
        float hn8[8];
#pragma unroll
        for (int k = 0; k < 8; k++) {
            float s = 0.f;
#pragma unroll
            for (int d = 0; d < 6; d++) s += h6[d] * sgw[d * 8 + k];
            hn8[k] = s;
        }
        float4* hnp = (float4*)(g_hn + gid * 8);
        hnp[0] = make_float4(hn8[0], hn8[1], hn8[2], hn8[3]);
        hnp[1] = make_float4(hn8[4], hn8[5], hn8[6], hn8[7]);
        float2 si, sj;
        si.x = hn8[0]*satt[0] + hn8[1]*satt[1] + hn8[2]*satt[2] + hn8[3]*satt[3];
        sj.x = hn8[0]*satt[4] + hn8[1]*satt[5] + hn8[2]*satt[6] + hn8[3]*satt[7];
        si.y = hn8[4]*satt[8] + hn8[5]*satt[9] + hn8[6]*satt[10] + hn8[7]*satt[11];
        sj.y = hn8[4]*satt[12] + hn8[5]*satt[13] + hn8[6]*satt[14] + hn8[7]*satt[15];
        ((float2*)g_si)[gid] = si;
        ((float2*)g_sj)[gid] = sj;
    } else {
        int e = (blockIdx.x - 256) * 256 + tid;
        int dst = eidx(ei, E_EDGES + e);
        int src = eidx(ei, e);
        int pos = atomicAdd(&g_cur[dst], 1);
        g_csr[pos] = src;
    }
}

// ---------------- L7: per-destination softmax + aggregate (single pass) ----------------
__global__ __launch_bounds__(128) void k_gat(const float* __restrict__ gbias) {
    int n = blockIdx.x;
    int tid = threadIdx.x;                        // (b,h,c): b=tid>>3, h=(tid>>2)&1, c=tid&3
    __shared__ float s_i_sh[32], s_red[128];
    __shared__ int srcs[128];
    if (tid < 32) s_i_sh[tid] = g_si[n * 32 + tid];
    __syncthreads();
    int base = g_off[n], deg = g_off[n + 1] - base;

    int bh = tid >> 2;
    float acc = 0.f, wsum = 0.f;
    float sib = s_i_sh[bh];
    for (int e0 = 0; e0 < deg; e0 += 128) {
        int m = min(128, deg - e0);
        if (tid < m) srcs[tid] = g_csr[base + e0 + tid];
        __syncthreads();
        for (int i = 0; i < m; i++) {
            int s = srcs[i];
            float a = sib + g_sj[s * 32 + bh];
            a = a >= 0.f ? a : 0.2f * a;
            a = fminf(fmaxf(a, -30.f), 30.f);     // tripwire only; scores are O(1)
            float w = __expf(a);
            wsum += w;
            acc += w * g_hn[s * 128 + tid];
        }
        __syncthreads();
    }
    float r = (wsum > 0.f) ? acc / (wsum * (float)deg) : 0.f;
    s_red[tid] = r;
    __syncthreads();
    if (tid < 64) {
        int b = tid >> 2, c = tid & 3;
        float v = 0.5f * (s_red[b * 8 + c] + s_red[b * 8 + 4 + c]) + gbias[c];
        g_o[b * 16384 + c * 4096 + n] = lrelu(v, 0.01f);
    }
}

// ---------------- L8: readout ----------------
__global__ __launch_bounds__(256) void k_readout(const float* __restrict__ ow, float* __restrict__ out) {
    int k = blockIdx.x, sl = blockIdx.y;
    int tid = threadIdx.x;
    float acc[16];
#pragma unroll
    for (int b = 0; b < 16; b++) acc[b] = 0.f;
    const float* wk = ow + k * 16384 + sl * 4096;
    const float* op = g_o + sl * 4096;
    for (int it = 0; it < 16; it++) {
        int i = tid + it * 256;
        float w = wk[i];
#pragma unroll
        for (int b = 0; b < 16; b++) acc[b] += w * op[b * 16384 + i];
    }
    __shared__ float red[8][16];
    int lane = tid & 31, wid = tid >> 5;
#pragma unroll
    for (int b = 0; b < 16; b++) {
        float v = acc[b];
#pragma unroll
        for (int o = 16; o; o >>= 1) v += __shfl_xor_sync(0xffffffffu, v, o);
        if (lane == 0) red[wid][b] = v;
    }
    __syncthreads();
    if (tid < 16) {
        float s = 0.f;
#pragma unroll
        for (int w = 0; w < 8; w++) s += red[w][tid];
        atomicAdd(&out[tid * 32 + k], s);
    }
}

// ---------------- launch ----------------
extern "C" void kernel_launch(void* const* d_in, const int* in_sizes, int n_in,
                              void* d_out, int out_size) {
    const float* x    = (const float*)d_in[0];
    const int*   ei   = (const int*)  d_in[1];
    const float* Wsub = (const float*)d_in[2];
    const float* bsub = (const float*)d_in[3];
    const float* fw   = (const float*)d_in[4];
    const float* mr   = (const float*)d_in[5];
    const float* fb   = (const float*)d_in[6];
    const float* gw   = (const float*)d_in[7];
    const float* gatt = (const float*)d_in[8];
    const float* gb   = (const float*)d_in[9];
    const float* ow   = (const float*)d_in[10];
    const float* ob   = (const float*)d_in[11];
    float* out = (float*)d_out;

    k_init<<<65, 256>>>(ei, bsub);                 // 1
    k_subnet<<<dim3(256, 4, 2), 256>>>(x, Wsub);   // 2
    k_pre<<<832, 256>>>(ei, mr);                   // 3  (mask compaction + hist + lrelu x)
    k_fcs<<<2048, 256>>>(fw, fb);                  // 4  <- profiled launch
    k_scan<<<1, 32>>>(out, ob);                    // 5
    k_mid<<<512, 256>>>(gw, gatt, ei);             // 6
    k_gat<<<4096, 128>>>(gb);                      // 7
    k_readout<<<dim3(32, 4), 256>>>(ow, out);      // 8
}

// round 7
// speedup vs baseline: 1.2764x; 1.0180x over previous
#include <cuda_runtime.h>

#define E_EDGES 65536
#define NGO 4096
#define B_SZ 16
#define G_SZ 1024

// ---------------- scratch (__device__ globals; no allocs allowed) ----------------
__device__ float g_xcat[B_SZ * G_SZ];        // [B][G]  (pre-lrelu, bias-initialized)
__device__ float g_xr[B_SZ * G_SZ];          // lrelu(g_xcat)
__device__ float g_h[NGO * 96];              // [N][B][6]
__device__ float g_hn[NGO * 128];            // [N][B][2][4]
__device__ float g_si[NGO * 32];             // [N][B][2]
__device__ float g_sj[NGO * 32];             // [N][B][2]
__device__ float g_o[B_SZ * 16384];          // [B][C*N]  (lrelu applied)
__device__ int   g_idxcnt[NGO];              // nnz count per mask group
__device__ int   g_idxbuf[NGO * 1024];       // nnz gene indices per mask group
__device__ int   g_cnt[NGO];                 // zero-init; k_scan re-zeroes each call
__device__ int   g_off[NGO + 1];
__device__ int   g_cur[NGO];
__device__ int   g_csr[E_EDGES];             // src per CSR slot
__device__ int   g_eflag;                    // 1 = edge_index is int64

__device__ __forceinline__ float lrelu(float x, float s) { return x >= 0.f ? x : s * x; }

// ---------------- L1: fused init (edge dtype detect + xcat=bias) ----------------
__global__ void k_init(const int* __restrict__ ei, const float* __restrict__ bsub) {
    int bid = blockIdx.x, tid = threadIdx.x;
    if (bid < 64) {
        int i = bid * 256 + tid;                 // 0..16383 = b*1024+g
        g_xcat[i] = bsub[i & 1023];
    } else {
        // int64 little-endian with values < 4096 -> every odd 32-bit word is 0.
        int ok = (ei[2 * tid + 1] == 0);
        int all = __syncthreads_and(ok);
        if (tid == 0) g_eflag = all;
    }
}
__device__ __forceinline__ int eidx(const int* __restrict__ p, int i) {
    return g_eflag ? p[2 * i] : p[i];
}

// ---------------- L2: per-gene subnet. block = 4 genes x 64 t x 8 b ----------------
__global__ __launch_bounds__(256) void k_subnet(const float* __restrict__ x,
                                                const float* __restrict__ Wsub) {
    int g0 = blockIdx.x * 4;
    int tid = threadIdx.x;
    int c = tid & 15, tr = tid >> 4;             // c: 16 consecutive float4 cols (256B)
    int gene = g0 + (c >> 2), pq = c & 3;
    int b0 = blockIdx.z * 8;
    const float4* x4 = (const float4*)x;
    const float4* w4 = (const float4*)Wsub;
    float acc[8];
#pragma unroll
    for (int b = 0; b < 8; b++) acc[b] = 0.f;
    int tbase = blockIdx.y * 64;
#pragma unroll 1
    for (int pass = 0; pass < 4; pass++) {
        int t = tbase + pass * 16 + tr;
        float4 w = w4[gene * 1024 + t * 4 + pq];
        int xoff = t * 4096 + g0 * 4 + c;
#pragma unroll
        for (int b = 0; b < 8; b++) {
            float4 xv = x4[(b0 + b) * 1048576 + xoff];
            acc[b] += w.x * xv.x + w.y * xv.y + w.z * xv.z + w.w * xv.w;
        }
    }
    __shared__ float red[8][4][8];
    int lane = tid & 31, wid = tid >> 5;
#pragma unroll
    for (int b = 0; b < 8; b++) {
        float v = acc[b];
        v += __shfl_xor_sync(0xffffffffu, v, 16);
        v += __shfl_xor_sync(0xffffffffu, v, 2);
        v += __shfl_xor_sync(0xffffffffu, v, 1);
        if ((lane & 3) == 0 && lane < 16) red[wid][lane >> 2][b] = v;
    }
    __syncthreads();
    if (tid < 32) {
        int gl = tid >> 3, b = tid & 7;
        float s = 0.f;
#pragma unroll
        for (int w2 = 0; w2 < 8; w2++) s += red[w2][gl][b];
        atomicAdd(&g_xcat[(b0 + b) * G_SZ + g0 + gl], s);
    }
}

// ---------------- L3: fused prep (mask nnz compaction + dst histogram + lrelu x) ----------------
__global__ void k_pre(const int* __restrict__ ei, const float* __restrict__ mr) {
    int bid = blockIdx.x, tid = threadIdx.x;
    if (bid < 512) {
        // warp per mask group: compact nonzero gene indices of mask row 6*grp
        int grp = bid * 8 + (tid >> 5), lane = tid & 31;
        const float* row = mr + (size_t)grp * 6144;   // rows 6g..6g+5 identical
        int* out = g_idxbuf + grp * 1024;
        int cnt = 0;
#pragma unroll 4
        for (int c = 0; c < 32; c++) {
            float v = row[c * 32 + lane];
            unsigned ball = __ballot_sync(0xffffffffu, v != 0.f);
            if (v != 0.f) out[cnt + __popc(ball & ((1u << lane) - 1u))] = c * 32 + lane;
            cnt += __popc(ball);
        }
        if (lane == 0) g_idxcnt[grp] = cnt;
    } else if (bid < 768) {
        int e = (bid - 512) * 256 + tid;
        int dst = eidx(ei, E_EDGES + e);
        atomicAdd(&g_cnt[dst], 1);
    } else {
        int i = (bid - 768) * 256 + tid;             // 0..16383
        g_xr[i] = lrelu(g_xcat[i], 0.01f);
    }
}

// ---------------- L4 (PROFILED): sparse masked FC. warp = (group, 8 b's) ----------------
__global__ __launch_bounds__(256) void k_fcs(const float* __restrict__ fw,
                                             const float* __restrict__ fb) {
    int tid = threadIdx.x, wid = tid >> 5, lane = tid & 31;
    int grp = blockIdx.x * 4 + (wid >> 1);           // 0..4095; 2 warps per group, same block
    int b0 = (wid & 1) * 8;                          // 8 b's per warp
    int cnt = g_idxcnt[grp];
    const int* idx = g_idxbuf + grp * 1024;
    const float* wb = fw + (size_t)grp * 6144;
    float acc[6][8];
#pragma unroll
    for (int r = 0; r < 6; r++)
#pragma unroll
        for (int b = 0; b < 8; b++) acc[r][b] = 0.f;

    for (int k0 = 0; k0 < cnt; k0 += 32) {
        int kk = k0 + lane;
        bool on = kk < cnt;
        int g = on ? idx[kk] : 0;
        float xv[8];
#pragma unroll
        for (int b = 0; b < 8; b++) xv[b] = on ? g_xr[(b0 + b) * G_SZ + g] : 0.f;
#pragma unroll
        for (int r = 0; r < 6; r++) {
            float wv = on ? wb[r * 1024 + g] : 0.f;
#pragma unroll
            for (int b = 0; b < 8; b++) acc[r][b] += wv * xv[b];
        }
    }
#pragma unroll
    for (int r = 0; r < 6; r++) {
#pragma unroll
        for (int b = 0; b < 8; b++) {
            float v = acc[r][b];
#pragma unroll
            for (int o = 16; o; o >>= 1) v += __shfl_xor_sync(0xffffffffu, v, o);
            if (lane == 0) {
                int j = grp * 6 + r;
                int d = j >> 12, n = j & 4095;
                g_h[n * 96 + (b0 + b) * 6 + d] = lrelu(v + fb[j], 0.01f);
            }
        }
    }
}

// ---------------- L5: parallel scan (+ re-zero cnt, + out bias init) ----------------
__global__ __launch_bounds__(256) void k_scan(float* __restrict__ out, const float* __restrict__ ob) {
    int tid = threadIdx.x, lane = tid & 31, wid = tid >> 5;
    int base = tid * 16;
    int c[16];
    const int4* cp = (const int4*)&g_cnt[base];
#pragma unroll
    for (int q = 0; q < 4; q++) {
        int4 v = cp[q];
        c[q * 4 + 0] = v.x; c[q * 4 + 1] = v.y; c[q * 4 + 2] = v.z; c[q * 4 + 3] = v.w;
    }
    int loc[16], s = 0;
#pragma unroll
    for (int i = 0; i < 16; i++) { loc[i] = s; s += c[i]; }
    int v = s;
#pragma unroll
    for (int d = 1; d < 32; d <<= 1) {
        int o = __shfl_up_sync(0xffffffffu, v, d);
        if (lane >= d) v += o;
    }
    __shared__ int wsum[8];
    if (lane == 31) wsum[wid] = v;
    __syncthreads();
    int wbase = 0;
#pragma unroll
    for (int w = 0; w < 8; w++) wbase += (w < wid) ? wsum[w] : 0;
    int excl = wbase + v - s;                     // exclusive prefix for this thread's 16
#pragma unroll
    for (int i = 0; i < 16; i++) {
        int e = excl + loc[i];
        g_off[base + i] = e;
        g_cur[base + i] = e;
        g_cnt[base + i] = 0;                      // ready for next replay
    }
    if (tid == 255) g_off[NGO] = excl + s;
    for (int i = tid; i < 512; i += 256) out[i] = ob[i & 31];
}

// ---------------- L6: fused GAT projection + CSR scatter ----------------
__global__ void k_mid(const float* __restrict__ gw, const float* __restrict__ gatt,
                      const int* __restrict__ ei) {
    int tid = threadIdx.x;
    if (blockIdx.x < 256) {
        __shared__ float sgw[48], satt[16];
        if (tid < 48) sgw[tid] = gw[tid];
        if (tid < 16) satt[tid] = gatt[tid];
        __syncthreads();
        int gid = blockIdx.x * 256 + tid;         // n*16 + b
        const float2* hp = (const float2*)(g_h + gid * 6);
        float2 h01 = hp[0], h23 = hp[1], h45 = hp[2];
        float h6[6] = {h01.x, h01.y, h23.x, h23.y, h45.x, h45.y};
        float hn8[8];
#pragma unroll
        for (int k = 0; k < 8; k++) {
            float s = 0.f;
#pragma unroll
            for (int d = 0; d < 6; d++) s += h6[d] * sgw[d * 8 + k];
            hn8[k] = s;
        }
        float4* hnp = (float4*)(g_hn + gid * 8);
        hnp[0] = make_float4(hn8[0], hn8[1], hn8[2], hn8[3]);
        hnp[1] = make_float4(hn8[4], hn8[5], hn8[6], hn8[7]);
        float2 si, sj;
        si.x = hn8[0]*satt[0] + hn8[1]*satt[1] + hn8[2]*satt[2] + hn8[3]*satt[3];
        sj.x = hn8[0]*satt[4] + hn8[1]*satt[5] + hn8[2]*satt[6] + hn8[3]*satt[7];
        si.y = hn8[4]*satt[8] + hn8[5]*satt[9] + hn8[6]*satt[10] + hn8[7]*satt[11];
        sj.y = hn8[4]*satt[12] + hn8[5]*satt[13] + hn8[6]*satt[14] + hn8[7]*satt[15];
        ((float2*)g_si)[gid] = si;
        ((float2*)g_sj)[gid] = sj;
    } else {
        int e = (blockIdx.x - 256) * 256 + tid;
        int dst = eidx(ei, E_EDGES + e);
        int src = eidx(ei, e);
        int pos = atomicAdd(&g_cur[dst], 1);
        g_csr[pos] = src;
    }
}

// ---------------- L7: per-destination softmax + aggregate (single pass) ----------------
__global__ __launch_bounds__(128) void k_gat(const float* __restrict__ gbias) {
    int n = blockIdx.x;
    int tid = threadIdx.x;                        // (b,h,c): b=tid>>3, h=(tid>>2)&1, c=tid&3
    __shared__ float s_i_sh[32], s_red[128];
    __shared__ int srcs[128];
    if (tid < 32) s_i_sh[tid] = g_si[n * 32 + tid];
    __syncthreads();
    int base = g_off[n], deg = g_off[n + 1] - base;

    int bh = tid >> 2;
    float acc = 0.f, wsum = 0.f;
    float sib = s_i_sh[bh];
    for (int e0 = 0; e0 < deg; e0 += 128) {
        int m = min(128, deg - e0);
        if (tid < m) srcs[tid] = g_csr[base + e0 + tid];
        __syncthreads();
        for (int i = 0; i < m; i++) {
            int s = srcs[i];
            float a = sib + g_sj[s * 32 + bh];
            a = a >= 0.f ? a : 0.2f * a;
            a = fminf(fmaxf(a, -30.f), 30.f);     // tripwire only; scores are O(1)
            float w = __expf(a);
            wsum += w;
            acc += w * g_hn[s * 128 + tid];
        }
        __syncthreads();
    }
    float r = (wsum > 0.f) ? acc / (wsum * (float)deg) : 0.f;
    s_red[tid] = r;
    __syncthreads();
    if (tid < 64) {
        int b = tid >> 2, c = tid & 3;
        float v = 0.5f * (s_red[b * 8 + c] + s_red[b * 8 + 4 + c]) + gbias[c];
        g_o[b * 16384 + c * 4096 + n] = lrelu(v, 0.01f);
    }
}

// ---------------- L8: readout ----------------
__global__ __launch_bounds__(256) void k_readout(const float* __restrict__ ow, float* __restrict__ out) {
    int k = blockIdx.x, sl = blockIdx.y;
    int tid = threadIdx.x;
    float acc[16];
#pragma unroll
    for (int b = 0; b < 16; b++) acc[b] = 0.f;
    const float* wk = ow + k * 16384 + sl * 4096;
    const float* op = g_o + sl * 4096;
    for (int it = 0; it < 16; it++) {
        int i = tid + it * 256;
        float w = wk[i];
#pragma unroll
        for (int b = 0; b < 16; b++) acc[b] += w * op[b * 16384 + i];
    }
    __shared__ float red[8][16];
    int lane = tid & 31, wid = tid >> 5;
#pragma unroll
    for (int b = 0; b < 16; b++) {
        float v = acc[b];
#pragma unroll
        for (int o = 16; o; o >>= 1) v += __shfl_xor_sync(0xffffffffu, v, o);
        if (lane == 0) red[wid][b] = v;
    }
    __syncthreads();
    if (tid < 16) {
        float s = 0.f;
#pragma unroll
        for (int w = 0; w < 8; w++) s += red[w][tid];
        atomicAdd(&out[tid * 32 + k], s);
    }
}

// ---------------- launch ----------------
extern "C" void kernel_launch(void* const* d_in, const int* in_sizes, int n_in,
                              void* d_out, int out_size) {
    const float* x    = (const float*)d_in[0];
    const int*   ei   = (const int*)  d_in[1];
    const float* Wsub = (const float*)d_in[2];
    const float* bsub = (const float*)d_in[3];
    const float* fw   = (const float*)d_in[4];
    const float* mr   = (const float*)d_in[5];
    const float* fb   = (const float*)d_in[6];
    const float* gw   = (const float*)d_in[7];
    const float* gatt = (const float*)d_in[8];
    const float* gb   = (const float*)d_in[9];
    const float* ow   = (const float*)d_in[10];
    const float* ob   = (const float*)d_in[11];
    float* out = (float*)d_out;

    k_init<<<65, 256>>>(ei, bsub);                 // 1
    k_subnet<<<dim3(256, 4, 2), 256>>>(x, Wsub);   // 2
    k_pre<<<832, 256>>>(ei, mr);                   // 3
    k_fcs<<<1024, 256>>>(fw, fb);                  // 4  <- profiled launch
    k_scan<<<1, 256>>>(out, ob);                   // 5
    k_mid<<<512, 256>>>(gw, gatt, ei);             // 6
    k_gat<<<4096, 128>>>(gb);                      // 7
    k_readout<<<dim3(32, 4), 256>>>(ow, out);      // 8
}

// round 8
// speedup vs baseline: 1.3017x; 1.0198x over previous
#include <cuda_runtime.h>

#define E_EDGES 65536
#define NGO 4096
#define B_SZ 16
#define G_SZ 1024

// ---------------- scratch (__device__ globals; no allocs allowed) ----------------
__device__ float g_xcat[B_SZ * G_SZ];        // [B][G]  (pre-lrelu, bias-initialized)
__device__ float g_xr[B_SZ * G_SZ];          // lrelu(g_xcat)
__device__ float g_h[NGO * 96];              // [N][B][6]
__device__ float g_hn[NGO * 128];            // [N][B][2][4]
__device__ float g_si[NGO * 32];             // [N][B][2]
__device__ float g_sj[NGO * 32];             // [N][B][2]
__device__ float g_o[B_SZ * 16384];          // [B][C*N]  (lrelu applied)
__device__ int   g_idxcnt[NGO];              // nnz count per mask group
__device__ int   g_idxbuf[NGO * 1024];       // nnz gene indices per mask group
__device__ int   g_cnt[NGO];                 // zero-init; k_scan re-zeroes each call
__device__ int   g_off[NGO + 1];
__device__ int   g_cur[NGO];
__device__ int   g_csr[E_EDGES];             // src per CSR slot
__device__ int   g_eflag;                    // 1 = edge_index is int64

__device__ __forceinline__ float lrelu(float x, float s) { return x >= 0.f ? x : s * x; }

// ---------------- L1: fused init (edge dtype detect + xcat=bias) ----------------
__global__ void k_init(const int* __restrict__ ei, const float* __restrict__ bsub) {
    int bid = blockIdx.x, tid = threadIdx.x;
    if (bid < 64) {
        int i = bid * 256 + tid;                 // 0..16383 = b*1024+g
        g_xcat[i] = bsub[i & 1023];
    } else {
        // int64 little-endian with values < 4096 -> every odd 32-bit word is 0.
        int ok = (ei[2 * tid + 1] == 0);
        int all = __syncthreads_and(ok);
        if (tid == 0) g_eflag = all;
    }
}
__device__ __forceinline__ int eidx(const int* __restrict__ p, int i) {
    return g_eflag ? p[2 * i] : p[i];
}

// ---------------- L2: per-gene subnet. block = 4 genes x 64 t x 8 b ----------------
__global__ __launch_bounds__(256) void k_subnet(const float* __restrict__ x,
                                                const float* __restrict__ Wsub) {
    int g0 = blockIdx.x * 4;
    int tid = threadIdx.x;
    int c = tid & 15, tr = tid >> 4;             // c: 16 consecutive float4 cols (256B)
    int gene = g0 + (c >> 2), pq = c & 3;
    int b0 = blockIdx.z * 8;
    const float4* x4 = (const float4*)x;
    const float4* w4 = (const float4*)Wsub;
    float acc[8];
#pragma unroll
    for (int b = 0; b < 8; b++) acc[b] = 0.f;
    int tbase = blockIdx.y * 64;
#pragma unroll 1
    for (int pass = 0; pass < 4; pass++) {
        int t = tbase + pass * 16 + tr;
        float4 w = w4[gene * 1024 + t * 4 + pq];
        int xoff = t * 4096 + g0 * 4 + c;
#pragma unroll
        for (int b = 0; b < 8; b++) {
            float4 xv = x4[(b0 + b) * 1048576 + xoff];
            acc[b] += w.x * xv.x + w.y * xv.y + w.z * xv.z + w.w * xv.w;
        }
    }
    __shared__ float red[8][4][8];
    int lane = tid & 31, wid = tid >> 5;
#pragma unroll
    for (int b = 0; b < 8; b++) {
        float v = acc[b];
        v += __shfl_xor_sync(0xffffffffu, v, 16);
        v += __shfl_xor_sync(0xffffffffu, v, 2);
        v += __shfl_xor_sync(0xffffffffu, v, 1);
        if ((lane & 3) == 0 && lane < 16) red[wid][lane >> 2][b] = v;
    }
    __syncthreads();
    if (tid < 32) {
        int gl = tid >> 3, b = tid & 7;
        float s = 0.f;
#pragma unroll
        for (int w2 = 0; w2 < 8; w2++) s += red[w2][gl][b];
        atomicAdd(&g_xcat[(b0 + b) * G_SZ + g0 + gl], s);
    }
}

// ---------------- L3: fused prep (mask nnz compaction + dst histogram + lrelu x) ----------------
__global__ void k_pre(const int* __restrict__ ei, const float* __restrict__ mr) {
    int bid = blockIdx.x, tid = threadIdx.x;
    if (bid < 512) {
        // warp per mask group: compact nonzero gene indices of mask row 6*grp
        int grp = bid * 8 + (tid >> 5), lane = tid & 31;
        const float* row = mr + (size_t)grp * 6144;   // rows 6g..6g+5 identical
        int* out = g_idxbuf + grp * 1024;
        int cnt = 0;
#pragma unroll 4
        for (int c = 0; c < 32; c++) {
            float v = row[c * 32 + lane];
            unsigned ball = __ballot_sync(0xffffffffu, v != 0.f);
            if (v != 0.f) out[cnt + __popc(ball & ((1u << lane) - 1u))] = c * 32 + lane;
            cnt += __popc(ball);
        }
        if (lane == 0) g_idxcnt[grp] = cnt;
    } else if (bid < 768) {
        int e = (bid - 512) * 256 + tid;
        int dst = eidx(ei, E_EDGES + e);
        atomicAdd(&g_cnt[dst], 1);
    } else {
        int i = (bid - 768) * 256 + tid;             // 0..16383
        g_xr[i] = lrelu(g_xcat[i], 0.01f);
    }
}

// ---------------- L4 (PROFILED): sparse masked FC with smem weight staging ----------------
// block = 2 groups x 128 thr; per group: stage (idx, 6 w-rows) to smem once,
// then 4 warps (4 b's each) compute from smem + L1-resident g_xr gathers.
__global__ __launch_bounds__(256) void k_fcs(const float* __restrict__ fw,
                                             const float* __restrict__ fb) {
    __shared__ int   s_idx[2][128];
    __shared__ float s_w[2][6][128];
    int tid = threadIdx.x;
    int grp_l = tid >> 7, tg = tid & 127;            // group-local id
    int wid_g = tg >> 5, lane = tid & 31;            // warp within group, lane
    int grp = blockIdx.x * 2 + grp_l;
    int cnt0 = g_idxcnt[blockIdx.x * 2];
    int cnt1 = g_idxcnt[blockIdx.x * 2 + 1];
    int cnt = grp_l ? cnt1 : cnt0;
    int cntmax = max(cnt0, cnt1);
    const int* idx = g_idxbuf + grp * 1024;
    const float* wb = fw + (size_t)grp * 6144;
    int b0 = wid_g * 4;
    float acc[6][4];
#pragma unroll
    for (int r = 0; r < 6; r++)
#pragma unroll
        for (int b = 0; b < 4; b++) acc[r][b] = 0.f;

    for (int k0 = 0; k0 < cntmax; k0 += 128) {
        int m = min(128, cnt - k0);                  // may be <=0 for this group
        if (tg < m) {
            int g = idx[k0 + tg];
            s_idx[grp_l][tg] = g;
#pragma unroll
            for (int r = 0; r < 6; r++) s_w[grp_l][r][tg] = wb[r * 1024 + g];
        }
        __syncthreads();
        for (int i = lane; i < m; i += 32) {
            int g = s_idx[grp_l][i];
            float xv[4];
#pragma unroll
            for (int b = 0; b < 4; b++) xv[b] = g_xr[(b0 + b) * G_SZ + g];
#pragma unroll
            for (int r = 0; r < 6; r++) {
                float wv = s_w[grp_l][r][i];
#pragma unroll
                for (int b = 0; b < 4; b++) acc[r][b] += wv * xv[b];
            }
        }
        __syncthreads();
    }
#pragma unroll
    for (int r = 0; r < 6; r++) {
#pragma unroll
        for (int b = 0; b < 4; b++) {
            float v = acc[r][b];
#pragma unroll
            for (int o = 16; o; o >>= 1) v += __shfl_xor_sync(0xffffffffu, v, o);
            if (lane == 0) {
                int j = grp * 6 + r;
                int d = j >> 12, n = j & 4095;
                g_h[n * 96 + (b0 + b) * 6 + d] = lrelu(v + fb[j], 0.01f);
            }
        }
    }
}

// ---------------- L5: parallel scan (+ re-zero cnt, + out bias init) ----------------
__global__ __launch_bounds__(256) void k_scan(float* __restrict__ out, const float* __restrict__ ob) {
    int tid = threadIdx.x, lane = tid & 31, wid = tid >> 5;
    int base = tid * 16;
    int c[16];
    const int4* cp = (const int4*)&g_cnt[base];
#pragma unroll
    for (int q = 0; q < 4; q++) {
        int4 v = cp[q];
        c[q * 4 + 0] = v.x; c[q * 4 + 1] = v.y; c[q * 4 + 2] = v.z; c[q * 4 + 3] = v.w;
    }
    int loc[16], s = 0;
#pragma unroll
    for (int i = 0; i < 16; i++) { loc[i] = s; s += c[i]; }
    int v = s;
#pragma unroll
    for (int d = 1; d < 32; d <<= 1) {
        int o = __shfl_up_sync(0xffffffffu, v, d);
        if (lane >= d) v += o;
    }
    __shared__ int wsum[8];
    if (lane == 31) wsum[wid] = v;
    __syncthreads();
    int wbase = 0;
#pragma unroll
    for (int w = 0; w < 8; w++) wbase += (w < wid) ? wsum[w] : 0;
    int excl = wbase + v - s;                     // exclusive prefix for this thread's 16
#pragma unroll
    for (int i = 0; i < 16; i++) {
        int e = excl + loc[i];
        g_off[base + i] = e;
        g_cur[base + i] = e;
        g_cnt[base + i] = 0;                      // ready for next replay
    }
    if (tid == 255) g_off[NGO] = excl + s;
    for (int i = tid; i < 512; i += 256) out[i] = ob[i & 31];
}

// ---------------- L6: fused GAT projection + CSR scatter ----------------
__global__ void k_mid(const float* __restrict__ gw, const float* __restrict__ gatt,
                      const int* __restrict__ ei) {
    int tid = threadIdx.x;
    if (blockIdx.x < 256) {
        __shared__ float sgw[48], satt[16];
        if (tid < 48) sgw[tid] = gw[tid];
        if (tid < 16) satt[tid] = gatt[tid];
        __syncthreads();
        int gid = blockIdx.x * 256 + tid;         // n*16 + b
        const float2* hp = (const float2*)(g_h + gid * 6);
        float2 h01 = hp[0], h23 = hp[1], h45 = hp[2];
        float h6[6] = {h01.x, h01.y, h23.x, h23.y, h45.x, h45.y};
        float hn8[8];
#pragma unroll
        for (int k = 0; k < 8; k++) {
            float s = 0.f;
#pragma unroll
            for (int d = 0; d < 6; d++) s += h6[d] * sgw[d * 8 + k];
            hn8[k] = s;
        }
        float4* hnp = (float4*)(g_hn + gid * 8);
        hnp[0] = make_float4(hn8[0], hn8[1], hn8[2], hn8[3]);
        hnp[1] = make_float4(hn8[4], hn8[5], hn8[6], hn8[7]);
        float2 si, sj;
        si.x = hn8[0]*satt[0] + hn8[1]*satt[1] + hn8[2]*satt[2] + hn8[3]*satt[3];
        sj.x = hn8[0]*satt[4] + hn8[1]*satt[5] + hn8[2]*satt[6] + hn8[3]*satt[7];
        si.y = hn8[4]*satt[8] + hn8[5]*satt[9] + hn8[6]*satt[10] + hn8[7]*satt[11];
        sj.y = hn8[4]*satt[12] + hn8[5]*satt[13] + hn8[6]*satt[14] + hn8[7]*satt[15];
        ((float2*)g_si)[gid] = si;
        ((float2*)g_sj)[gid] = sj;
    } else {
        int e = (blockIdx.x - 256) * 256 + tid;
        int dst = eidx(ei, E_EDGES + e);
        int src = eidx(ei, e);
        int pos = atomicAdd(&g_cur[dst], 1);
        g_csr[pos] = src;
    }
}

// ---------------- L7: per-destination softmax + aggregate (single pass) ----------------
__global__ __launch_bounds__(128) void k_gat(const float* __restrict__ gbias) {
    int n = blockIdx.x;
    int tid = threadIdx.x;                        // (b,h,c): b=tid>>3, h=(tid>>2)&1, c=tid&3
    __shared__ float s_i_sh[32], s_red[128];
    __shared__ int srcs[128];
    if (tid < 32) s_i_sh[tid] = g_si[n * 32 + tid];
    __syncthreads();
    int base = g_off[n], deg = g_off[n + 1] - base;

    int bh = tid >> 2;
    float acc = 0.f, wsum = 0.f;
    float sib = s_i_sh[bh];
    for (int e0 = 0; e0 < deg; e0 += 128) {
        int m = min(128, deg - e0);
        if (tid < m) srcs[tid] = g_csr[base + e0 + tid];
        __syncthreads();
        for (int i = 0; i < m; i++) {
            int s = srcs[i];
            float a = sib + g_sj[s * 32 + bh];
            a = a >= 0.f ? a : 0.2f * a;
            a = fminf(fmaxf(a, -30.f), 30.f);     // tripwire only; scores are O(1)
            float w = __expf(a);
            wsum += w;
            acc += w * g_hn[s * 128 + tid];
        }
        __syncthreads();
    }
    float r = (wsum > 0.f) ? acc / (wsum * (float)deg) : 0.f;
    s_red[tid] = r;
    __syncthreads();
    if (tid < 64) {
        int b = tid >> 2, c = tid & 3;
        float v = 0.5f * (s_red[b * 8 + c] + s_red[b * 8 + 4 + c]) + gbias[c];
        g_o[b * 16384 + c * 4096 + n] = lrelu(v, 0.01f);
    }
}

// ---------------- L8: readout ----------------
__global__ __launch_bounds__(256) void k_readout(const float* __restrict__ ow, float* __restrict__ out) {
    int k = blockIdx.x, sl = blockIdx.y;
    int tid = threadIdx.x;
    float acc[16];
#pragma unroll
    for (int b = 0; b < 16; b++) acc[b] = 0.f;
    const float* wk = ow + k * 16384 + sl * 4096;
    const float* op = g_o + sl * 4096;
    for (int it = 0; it < 16; it++) {
        int i = tid + it * 256;
        float w = wk[i];
#pragma unroll
        for (int b = 0; b < 16; b++) acc[b] += w * op[b * 16384 + i];
    }
    __shared__ float red[8][16];
    int lane = tid & 31, wid = tid >> 5;
#pragma unroll
    for (int b = 0; b < 16; b++) {
        float v = acc[b];
#pragma unroll
        for (int o = 16; o; o >>= 1) v += __shfl_xor_sync(0xffffffffu, v, o);
        if (lane == 0) red[wid][b] = v;
    }
    __syncthreads();
    if (tid < 16) {
        float s = 0.f;
#pragma unroll
        for (int w = 0; w < 8; w++) s += red[w][tid];
        atomicAdd(&out[tid * 32 + k], s);
    }
}

// ---------------- launch ----------------
extern "C" void kernel_launch(void* const* d_in, const int* in_sizes, int n_in,
                              void* d_out, int out_size) {
    const float* x    = (const float*)d_in[0];
    const int*   ei   = (const int*)  d_in[1];
    const float* Wsub = (const float*)d_in[2];
    const float* bsub = (const float*)d_in[3];
    const float* fw   = (const float*)d_in[4];
    const float* mr   = (const float*)d_in[5];
    const float* fb   = (const float*)d_in[6];
    const float* gw   = (const float*)d_in[7];
    const float* gatt = (const float*)d_in[8];
    const float* gb   = (const float*)d_in[9];
    const float* ow   = (const float*)d_in[10];
    const float* ob   = (const float*)d_in[11];
    float* out = (float*)d_out;

    k_init<<<65, 256>>>(ei, bsub);                 // 1
    k_subnet<<<dim3(256, 4, 2), 256>>>(x, Wsub);   // 2
    k_pre<<<832, 256>>>(ei, mr);                   // 3
    k_fcs<<<2048, 256>>>(fw, fb);                  // 4  <- profiled launch
    k_scan<<<1, 256>>>(out, ob);                   // 5
    k_mid<<<512, 256>>>(gw, gatt, ei);             // 6
    k_gat<<<4096, 128>>>(gb);                      // 7
    k_readout<<<dim3(32, 4), 256>>>(ow, out);      // 8
}

// round 9
// speedup vs baseline: 1.3600x; 1.0448x over previous
#include <cuda_runtime.h>

#define E_EDGES 65536
#define NGO 4096
#define B_SZ 16
#define G_SZ 1024

// ---------------- scratch (__device__ globals; no allocs allowed) ----------------
__device__ float g_xcat[B_SZ * G_SZ];        // [B][G] partial sums; zeroed by k_gat for next run
__device__ float g_h[NGO * 96];              // [N][B][6]
__device__ float g_hn[NGO * 128];            // [N][B][2][4]
__device__ float g_si[NGO * 32];             // [N][B][2]
__device__ float g_sj[NGO * 32];             // [N][B][2]
__device__ float g_o[B_SZ * 16384];          // [B][C*N]  (lrelu applied)
__device__ float g_wpk[NGO * 6 * 128];       // packed masked weights [grp][6][128]
__device__ int   g_idxcnt[NGO];              // nnz count per mask group
__device__ int   g_idxbuf[NGO * 1024];       // nnz gene indices per mask group
__device__ int   g_cnt[NGO];                 // zero-init; k_scan role re-zeroes each run
__device__ int   g_off[NGO + 1];
__device__ int   g_cur[NGO];
__device__ int   g_csr[E_EDGES];             // src per CSR slot

__device__ __forceinline__ float lrelu(float x, float s) { return x >= 0.f ? x : s * x; }

// ---------------- L1: mega-kernel — subnet + mask-compact/weight-pack + histogram ----
// blocks [0,2048): subnet; [2048,2560): prep (compact + pack); [2560,2624): hist
__global__ __launch_bounds__(256) void k_main1(const float* __restrict__ x,
                                               const float* __restrict__ Wsub,
                                               const float* __restrict__ fw,
                                               const float* __restrict__ mr,
                                               const int* __restrict__ ei) {
    int bid = blockIdx.x, tid = threadIdx.x;
    if (bid < 2048) {
        // ---- subnet: 4 genes x 64 t-rows x 8 b per block ----
        int bx = bid & 255, by = (bid >> 8) & 3, bz = bid >> 10;
        int g0 = bx * 4;
        int c = tid & 15, tr = tid >> 4;
        int gene = g0 + (c >> 2), pq = c & 3;
        int b0 = bz * 8;
        const float4* x4 = (const float4*)x;
        const float4* w4 = (const float4*)Wsub;
        float acc[8];
#pragma unroll
        for (int b = 0; b < 8; b++) acc[b] = 0.f;
        int tbase = by * 64;
#pragma unroll 1
        for (int pass = 0; pass < 4; pass++) {
            int t = tbase + pass * 16 + tr;
            float4 w = w4[gene * 1024 + t * 4 + pq];
            int xoff = t * 4096 + g0 * 4 + c;
#pragma unroll
            for (int b = 0; b < 8; b++) {
                float4 xv = x4[(b0 + b) * 1048576 + xoff];
                acc[b] += w.x * xv.x + w.y * xv.y + w.z * xv.z + w.w * xv.w;
            }
        }
        __shared__ float red[8][4][8];
        int lane = tid & 31, wid = tid >> 5;
#pragma unroll
        for (int b = 0; b < 8; b++) {
            float v = acc[b];
            v += __shfl_xor_sync(0xffffffffu, v, 16);
            v += __shfl_xor_sync(0xffffffffu, v, 2);
            v += __shfl_xor_sync(0xffffffffu, v, 1);
            if ((lane & 3) == 0 && lane < 16) red[wid][lane >> 2][b] = v;
        }
        __syncthreads();
        if (tid < 32) {
            int gl = tid >> 3, b = tid & 7;
            float s = 0.f;
#pragma unroll
            for (int w2 = 0; w2 < 8; w2++) s += red[w2][gl][b];
            atomicAdd(&g_xcat[(b0 + b) * G_SZ + g0 + gl], s);
        }
    } else if (bid < 2560) {
        // ---- prep: warp per group — compact mask row, pack 6 weight rows ----
        __shared__ int s_idx[8][128];
        int w = tid >> 5, lane = tid & 31;
        int grp = (bid - 2048) * 8 + w;
        const float* row = mr + (size_t)grp * 6144;   // rows 6g..6g+5 identical
        int* gout = g_idxbuf + grp * 1024;
        int cnt = 0;
#pragma unroll 4
        for (int c = 0; c < 32; c++) {
            float v = row[c * 32 + lane];
            unsigned ball = __ballot_sync(0xffffffffu, v != 0.f);
            if (v != 0.f) {
                int p = cnt + __popc(ball & ((1u << lane) - 1u));
                gout[p] = c * 32 + lane;
                if (p < 128) s_idx[w][p] = c * 32 + lane;
            }
            cnt += __popc(ball);
        }
        if (lane == 0) g_idxcnt[grp] = cnt;
        __syncwarp();
        const float* wb = fw + (size_t)grp * 6144;
        float* pk = g_wpk + grp * 768;
        int cend = min(cnt, 128);
        for (int k = lane; k < cend; k += 32) {
            int g = s_idx[w][k];
#pragma unroll
            for (int r = 0; r < 6; r++) pk[r * 128 + k] = wb[r * 1024 + g];
        }
    } else {
        // ---- hist: local int64/int32 detect + dst histogram ----
        int ok = (ei[2 * tid + 1] == 0);
        int ef = __syncthreads_and(ok);
        int e0 = (bid - 2560) * 1024;
#pragma unroll
        for (int it = 0; it < 4; it++) {
            int e = e0 + it * 256 + tid;
            int dst = ef ? ei[2 * (E_EDGES + e)] : ei[E_EDGES + e];
            atomicAdd(&g_cnt[dst], 1);
        }
    }
}

// ---------------- L2: packed-sparse FC (+ scan role) ----------------
// blocks [0,2048): 2 groups/block, 4 warps per group (4 b's each)
// block 2048: prefix scan of g_cnt + out bias init
__global__ __launch_bounds__(256) void k_fcs2(const float* __restrict__ fw,
                                              const float* __restrict__ fb,
                                              const float* __restrict__ bsub,
                                              float* __restrict__ out,
                                              const float* __restrict__ ob) {
    int tid = threadIdx.x;
    if (blockIdx.x < 2048) {
        int wid = tid >> 5, lane = tid & 31;
        int grp = blockIdx.x * 2 + (wid >> 2);
        int b0 = (wid & 3) * 4;
        int cnt = g_idxcnt[grp];
        const int* idx = g_idxbuf + grp * 1024;
        const float* pk = g_wpk + grp * 768;
        const float* wb = fw + (size_t)grp * 6144;
        float acc[6][4];
#pragma unroll
        for (int r = 0; r < 6; r++)
#pragma unroll
            for (int b = 0; b < 4; b++) acc[r][b] = 0.f;
        int cend = min(cnt, 128);
        for (int k = lane; k < cend; k += 32) {
            int g = idx[k];
            float bs = bsub[g];
            float xv[4];
#pragma unroll
            for (int b = 0; b < 4; b++) xv[b] = lrelu(g_xcat[(b0 + b) * G_SZ + g] + bs, 0.01f);
#pragma unroll
            for (int r = 0; r < 6; r++) {
                float wv = pk[r * 128 + k];
#pragma unroll
                for (int b = 0; b < 4; b++) acc[r][b] += wv * xv[b];
            }
        }
        if (cnt > 128) {                         // paranoia path; statistically never taken
            for (int k = 128 + lane; k < cnt; k += 32) {
                int g = idx[k];
                float bs = bsub[g];
                float xv[4];
#pragma unroll
                for (int b = 0; b < 4; b++) xv[b] = lrelu(g_xcat[(b0 + b) * G_SZ + g] + bs, 0.01f);
#pragma unroll
                for (int r = 0; r < 6; r++) {
                    float wv = wb[r * 1024 + g];
#pragma unroll
                    for (int b = 0; b < 4; b++) acc[r][b] += wv * xv[b];
                }
            }
        }
#pragma unroll
        for (int r = 0; r < 6; r++) {
#pragma unroll
            for (int b = 0; b < 4; b++) {
                float v = acc[r][b];
#pragma unroll
                for (int o = 16; o; o >>= 1) v += __shfl_xor_sync(0xffffffffu, v, o);
                if (lane == 0) {
                    int j = grp * 6 + r;
                    int d = j >> 12, n = j & 4095;
                    g_h[n * 96 + (b0 + b) * 6 + d] = lrelu(v + fb[j], 0.01f);
                }
            }
        }
    } else {
        // ---- scan role ----
        int lane = tid & 31, wid = tid >> 5;
        int base = tid * 16;
        int c[16];
        const int4* cp = (const int4*)&g_cnt[base];
#pragma unroll
        for (int q = 0; q < 4; q++) {
            int4 v = cp[q];
            c[q * 4 + 0] = v.x; c[q * 4 + 1] = v.y; c[q * 4 + 2] = v.z; c[q * 4 + 3] = v.w;
        }
        int loc[16], s = 0;
#pragma unroll
        for (int i = 0; i < 16; i++) { loc[i] = s; s += c[i]; }
        int v = s;
#pragma unroll
        for (int d = 1; d < 32; d <<= 1) {
            int o = __shfl_up_sync(0xffffffffu, v, d);
            if (lane >= d) v += o;
        }
        __shared__ int wsum[8];
        if (lane == 31) wsum[wid] = v;
        __syncthreads();
        int wbase = 0;
#pragma unroll
        for (int w = 0; w < 8; w++) wbase += (w < wid) ? wsum[w] : 0;
        int excl = wbase + v - s;
#pragma unroll
        for (int i = 0; i < 16; i++) {
            int e = excl + loc[i];
            g_off[base + i] = e;
            g_cur[base + i] = e;
            g_cnt[base + i] = 0;
        }
        if (tid == 255) g_off[NGO] = excl + s;
        for (int i = tid; i < 512; i += 256) out[i] = ob[i & 31];
    }
}

// ---------------- L3: fused GAT projection + CSR scatter ----------------
__global__ void k_mid(const float* __restrict__ gw, const float* __restrict__ gatt,
                      const int* __restrict__ ei) {
    int tid = threadIdx.x;
    if (blockIdx.x < 256) {
        __shared__ float sgw[48], satt[16];
        if (tid < 48) sgw[tid] = gw[tid];
        if (tid < 16) satt[tid] = gatt[tid];
        __syncthreads();
        int gid = blockIdx.x * 256 + tid;         // n*16 + b
        const float2* hp = (const float2*)(g_h + gid * 6);
        float2 h01 = hp[0], h23 = hp[1], h45 = hp[2];
        float h6[6] = {h01.x, h01.y, h23.x, h23.y, h45.x, h45.y};
        float hn8[8];
#pragma unroll
        for (int k = 0; k < 8; k++) {
            float s = 0.f;
#pragma unroll
            for (int d = 0; d < 6; d++) s += h6[d] * sgw[d * 8 + k];
            hn8[k] = s;
        }
        float4* hnp = (float4*)(g_hn + gid * 8);
        hnp[0] = make_float4(hn8[0], hn8[1], hn8[2], hn8[3]);
        hnp[1] = make_float4(hn8[4], hn8[5], hn8[6], hn8[7]);
        float2 si, sj;
        si.x = hn8[0]*satt[0] + hn8[1]*satt[1] + hn8[2]*satt[2] + hn8[3]*satt[3];
        sj.x = hn8[0]*satt[4] + hn8[1]*satt[5] + hn8[2]*satt[6] + hn8[3]*satt[7];
        si.y = hn8[4]*satt[8] + hn8[5]*satt[9] + hn8[6]*satt[10] + hn8[7]*satt[11];
        sj.y = hn8[4]*satt[12] + hn8[5]*satt[13] + hn8[6]*satt[14] + hn8[7]*satt[15];
        ((float2*)g_si)[gid] = si;
        ((float2*)g_sj)[gid] = sj;
    } else {
        int ok = (ei[2 * tid + 1] == 0);
        int ef = __syncthreads_and(ok);
        int e = (blockIdx.x - 256) * 256 + tid;
        int dst = ef ? ei[2 * (E_EDGES + e)] : ei[E_EDGES + e];
        int src = ef ? ei[2 * e] : ei[e];
        int pos = atomicAdd(&g_cur[dst], 1);
        g_csr[pos] = src;
    }
}

// ---------------- L4 (PROFILED): per-destination softmax + aggregate ----------------
// blocks [0,4096): GAT per dst; [4096,4128): zero g_xcat for next run
__global__ __launch_bounds__(128) void k_gat(const float* __restrict__ gbias) {
    int tid = threadIdx.x;
    if (blockIdx.x >= 4096) {
        ((float4*)g_xcat)[(blockIdx.x - 4096) * 128 + tid] = make_float4(0.f, 0.f, 0.f, 0.f);
        return;
    }
    int n = blockIdx.x;
    __shared__ float s_i_sh[32], s_red[128];
    __shared__ int srcs[128];
    if (tid < 32) s_i_sh[tid] = g_si[n * 32 + tid];
    __syncthreads();
    int base = g_off[n], deg = g_off[n + 1] - base;

    int bh = tid >> 2;
    float acc = 0.f, wsum = 0.f;
    float sib = s_i_sh[bh];
    for (int e0 = 0; e0 < deg; e0 += 128) {
        int m = min(128, deg - e0);
        if (tid < m) srcs[tid] = g_csr[base + e0 + tid];
        __syncthreads();
        for (int i = 0; i < m; i++) {
            int s = srcs[i];
            float a = sib + g_sj[s * 32 + bh];
            a = a >= 0.f ? a : 0.2f * a;
            a = fminf(fmaxf(a, -30.f), 30.f);     // tripwire only; scores are O(1)
            float w = __expf(a);
            wsum += w;
            acc += w * g_hn[s * 128 + tid];
        }
        __syncthreads();
    }
    float r = (wsum > 0.f) ? acc / (wsum * (float)deg) : 0.f;
    s_red[tid] = r;
    __syncthreads();
    if (tid < 64) {
        int b = tid >> 2, c = tid & 3;
        float v = 0.5f * (s_red[b * 8 + c] + s_red[b * 8 + 4 + c]) + gbias[c];
        g_o[b * 16384 + c * 4096 + n] = lrelu(v, 0.01f);
    }
}

// ---------------- L5: readout ----------------
__global__ __launch_bounds__(256) void k_readout(const float* __restrict__ ow, float* __restrict__ out) {
    int k = blockIdx.x, sl = blockIdx.y;
    int tid = threadIdx.x;
    float acc[16];
#pragma unroll
    for (int b = 0; b < 16; b++) acc[b] = 0.f;
    const float* wk = ow + k * 16384 + sl * 4096;
    const float* op = g_o + sl * 4096;
    for (int it = 0; it < 16; it++) {
        int i = tid + it * 256;
        float w = wk[i];
#pragma unroll
        for (int b = 0; b < 16; b++) acc[b] += w * op[b * 16384 + i];
    }
    __shared__ float red[8][16];
    int lane = tid & 31, wid = tid >> 5;
#pragma unroll
    for (int b = 0; b < 16; b++) {
        float v = acc[b];
#pragma unroll
        for (int o = 16; o; o >>= 1) v += __shfl_xor_sync(0xffffffffu, v, o);
        if (lane == 0) red[wid][b] = v;
    }
    __syncthreads();
    if (tid < 16) {
        float s = 0.f;
#pragma unroll
        for (int w = 0; w < 8; w++) s += red[w][tid];
        atomicAdd(&out[tid * 32 + k], s);
    }
}

// ---------------- launch ----------------
extern "C" void kernel_launch(void* const* d_in, const int* in_sizes, int n_in,
                              void* d_out, int out_size) {
    const float* x    = (const float*)d_in[0];
    const int*   ei   = (const int*)  d_in[1];
    const float* Wsub = (const float*)d_in[2];
    const float* bsub = (const float*)d_in[3];
    const float* fw   = (const float*)d_in[4];
    const float* mr   = (const float*)d_in[5];
    const float* fb   = (const float*)d_in[6];
    const float* gw   = (const float*)d_in[7];
    const float* gatt = (const float*)d_in[8];
    const float* gb   = (const float*)d_in[9];
    const float* ow   = (const float*)d_in[10];
    const float* ob   = (const float*)d_in[11];
    float* out = (float*)d_out;

    k_main1<<<2624, 256>>>(x, Wsub, fw, mr, ei);   // 1: subnet + prep + hist (overlapped)
    k_fcs2<<<2049, 256>>>(fw, fb, bsub, out, ob);  // 2: packed FC + scan
    k_mid<<<512, 256>>>(gw, gatt, ei);             // 3: proj + scatter
    k_gat<<<4128, 128>>>(gb);                      // 4: <- profiled launch (GAT + xcat zero)
    k_readout<<<dim3(32, 4), 256>>>(ow, out);      // 5
}

// round 10
// speedup vs baseline: 1.3805x; 1.0151x over previous
#include <cuda_runtime.h>

#define E_EDGES 65536
#define NGO 4096
#define B_SZ 16
#define G_SZ 1024

// ---------------- scratch (__device__ globals; no allocs allowed) ----------------
__device__ float g_xcat[B_SZ * G_SZ];        // [B][G] partial sums; zeroed by k_gat for next run
__device__ float g_h[NGO * 96];              // [N][B][6]
__device__ float g_hn[NGO * 128];            // [N][B][2][4]
__device__ float g_si[NGO * 32];             // [N][B][2]
__device__ float g_sj[NGO * 32];             // [N][B][2]
__device__ float g_o[B_SZ * 16384];          // [B][C*N]  (lrelu applied)
__device__ float g_wpk[NGO * 6 * 128];       // packed masked weights [grp][6][128]
__device__ int   g_idxcnt[NGO];              // nnz count per mask group
__device__ int   g_idxbuf[NGO * 1024];       // nnz gene indices per mask group
__device__ int   g_cnt[NGO];                 // zero-init; scan role re-zeroes each run
__device__ int   g_off[NGO + 1];
__device__ int   g_cur[NGO];
__device__ int   g_csr[E_EDGES];             // src per CSR slot

__device__ __forceinline__ float lrelu(float x, float s) { return x >= 0.f ? x : s * x; }

// ---------------- L1: mega-kernel — subnet + mask-compact/weight-pack + histogram ----
// blocks [0,2048): subnet; [2048,2560): prep (compact + pack); [2560,2624): hist
__global__ __launch_bounds__(256) void k_main1(const float* __restrict__ x,
                                               const float* __restrict__ Wsub,
                                               const float* __restrict__ fw,
                                               const float* __restrict__ mr,
                                               const int* __restrict__ ei) {
    int bid = blockIdx.x, tid = threadIdx.x;
    if (bid < 2048) {
        // ---- subnet: 4 genes x 64 t-rows x 8 b per block ----
        int bx = bid & 255, by = (bid >> 8) & 3, bz = bid >> 10;
        int g0 = bx * 4;
        int c = tid & 15, tr = tid >> 4;
        int gene = g0 + (c >> 2), pq = c & 3;
        int b0 = bz * 8;
        const float4* x4 = (const float4*)x;
        const float4* w4 = (const float4*)Wsub;
        float acc[8];
#pragma unroll
        for (int b = 0; b < 8; b++) acc[b] = 0.f;
        int tbase = by * 64;
#pragma unroll 1
        for (int pass = 0; pass < 4; pass++) {
            int t = tbase + pass * 16 + tr;
            float4 w = w4[gene * 1024 + t * 4 + pq];
            int xoff = t * 4096 + g0 * 4 + c;
#pragma unroll
            for (int b = 0; b < 8; b++) {
                float4 xv = x4[(b0 + b) * 1048576 + xoff];
                acc[b] += w.x * xv.x + w.y * xv.y + w.z * xv.z + w.w * xv.w;
            }
        }
        __shared__ float red[8][4][8];
        int lane = tid & 31, wid = tid >> 5;
#pragma unroll
        for (int b = 0; b < 8; b++) {
            float v = acc[b];
            v += __shfl_xor_sync(0xffffffffu, v, 16);
            v += __shfl_xor_sync(0xffffffffu, v, 2);
            v += __shfl_xor_sync(0xffffffffu, v, 1);
            if ((lane & 3) == 0 && lane < 16) red[wid][lane >> 2][b] = v;
        }
        __syncthreads();
        if (tid < 32) {
            int gl = tid >> 3, b = tid & 7;
            float s = 0.f;
#pragma unroll
            for (int w2 = 0; w2 < 8; w2++) s += red[w2][gl][b];
            atomicAdd(&g_xcat[(b0 + b) * G_SZ + g0 + gl], s);
        }
    } else if (bid < 2560) {
        // ---- prep: warp per group — compact mask row, pack 6 weight rows ----
        __shared__ int s_idx[8][128];
        int w = tid >> 5, lane = tid & 31;
        int grp = (bid - 2048) * 8 + w;
        const float* row = mr + (size_t)grp * 6144;   // rows 6g..6g+5 identical
        int* gout = g_idxbuf + grp * 1024;
        int cnt = 0;
#pragma unroll 4
        for (int c = 0; c < 32; c++) {
            float v = row[c * 32 + lane];
            unsigned ball = __ballot_sync(0xffffffffu, v != 0.f);
            if (v != 0.f) {
                int p = cnt + __popc(ball & ((1u << lane) - 1u));
                gout[p] = c * 32 + lane;
                if (p < 128) s_idx[w][p] = c * 32 + lane;
            }
            cnt += __popc(ball);
        }
        if (lane == 0) g_idxcnt[grp] = cnt;
        __syncwarp();
        const float* wb = fw + (size_t)grp * 6144;
        float* pk = g_wpk + grp * 768;
        int cend = min(cnt, 128);
        for (int k = lane; k < cend; k += 32) {
            int g = s_idx[w][k];
#pragma unroll
            for (int r = 0; r < 6; r++) pk[r * 128 + k] = wb[r * 1024 + g];
        }
    } else {
        // ---- hist: local int64/int32 detect + dst histogram ----
        int ok = (ei[2 * tid + 1] == 0);
        int ef = __syncthreads_and(ok);
        int e0 = (bid - 2560) * 1024;
#pragma unroll
        for (int it = 0; it < 4; it++) {
            int e = e0 + it * 256 + tid;
            int dst = ef ? ei[2 * (E_EDGES + e)] : ei[E_EDGES + e];
            atomicAdd(&g_cnt[dst], 1);
        }
    }
}

// ---------------- L2: packed-sparse FC (+ scan role) ----------------
__global__ __launch_bounds__(256) void k_fcs2(const float* __restrict__ fw,
                                              const float* __restrict__ fb,
                                              const float* __restrict__ bsub,
                                              float* __restrict__ out,
                                              const float* __restrict__ ob) {
    int tid = threadIdx.x;
    if (blockIdx.x < 2048) {
        int wid = tid >> 5, lane = tid & 31;
        int grp = blockIdx.x * 2 + (wid >> 2);
        int b0 = (wid & 3) * 4;
        int cnt = g_idxcnt[grp];
        const int* idx = g_idxbuf + grp * 1024;
        const float* pk = g_wpk + grp * 768;
        const float* wb = fw + (size_t)grp * 6144;
        float acc[6][4];
#pragma unroll
        for (int r = 0; r < 6; r++)
#pragma unroll
            for (int b = 0; b < 4; b++) acc[r][b] = 0.f;
        int cend = min(cnt, 128);
        for (int k = lane; k < cend; k += 32) {
            int g = idx[k];
            float bs = bsub[g];
            float xv[4];
#pragma unroll
            for (int b = 0; b < 4; b++) xv[b] = lrelu(g_xcat[(b0 + b) * G_SZ + g] + bs, 0.01f);
#pragma unroll
            for (int r = 0; r < 6; r++) {
                float wv = pk[r * 128 + k];
#pragma unroll
                for (int b = 0; b < 4; b++) acc[r][b] += wv * xv[b];
            }
        }
        if (cnt > 128) {                         // paranoia path; statistically never taken
            for (int k = 128 + lane; k < cnt; k += 32) {
                int g = idx[k];
                float bs = bsub[g];
                float xv[4];
#pragma unroll
                for (int b = 0; b < 4; b++) xv[b] = lrelu(g_xcat[(b0 + b) * G_SZ + g] + bs, 0.01f);
#pragma unroll
                for (int r = 0; r < 6; r++) {
                    float wv = wb[r * 1024 + g];
#pragma unroll
                    for (int b = 0; b < 4; b++) acc[r][b] += wv * xv[b];
                }
            }
        }
#pragma unroll
        for (int r = 0; r < 6; r++) {
#pragma unroll
            for (int b = 0; b < 4; b++) {
                float v = acc[r][b];
#pragma unroll
                for (int o = 16; o; o >>= 1) v += __shfl_xor_sync(0xffffffffu, v, o);
                if (lane == 0) {
                    int j = grp * 6 + r;
                    int d = j >> 12, n = j & 4095;
                    g_h[n * 96 + (b0 + b) * 6 + d] = lrelu(v + fb[j], 0.01f);
                }
            }
        }
    } else {
        // ---- scan role ----
        int lane = tid & 31, wid = tid >> 5;
        int base = tid * 16;
        int c[16];
        const int4* cp = (const int4*)&g_cnt[base];
#pragma unroll
        for (int q = 0; q < 4; q++) {
            int4 v = cp[q];
            c[q * 4 + 0] = v.x; c[q * 4 + 1] = v.y; c[q * 4 + 2] = v.z; c[q * 4 + 3] = v.w;
        }
        int loc[16], s = 0;
#pragma unroll
        for (int i = 0; i < 16; i++) { loc[i] = s; s += c[i]; }
        int v = s;
#pragma unroll
        for (int d = 1; d < 32; d <<= 1) {
            int o = __shfl_up_sync(0xffffffffu, v, d);
            if (lane >= d) v += o;
        }
        __shared__ int wsum[8];
        if (lane == 31) wsum[wid] = v;
        __syncthreads();
        int wbase = 0;
#pragma unroll
        for (int w = 0; w < 8; w++) wbase += (w < wid) ? wsum[w] : 0;
        int excl = wbase + v - s;
#pragma unroll
        for (int i = 0; i < 16; i++) {
            int e = excl + loc[i];
            g_off[base + i] = e;
            g_cur[base + i] = e;
            g_cnt[base + i] = 0;
        }
        if (tid == 255) g_off[NGO] = excl + s;
        for (int i = tid; i < 512; i += 256) out[i] = ob[i & 31];
    }
}

// ---------------- L3: fused GAT projection + CSR scatter ----------------
__global__ void k_mid(const float* __restrict__ gw, const float* __restrict__ gatt,
                      const int* __restrict__ ei) {
    int tid = threadIdx.x;
    if (blockIdx.x < 256) {
        __shared__ float sgw[48], satt[16];
        if (tid < 48) sgw[tid] = gw[tid];
        if (tid < 16) satt[tid] = gatt[tid];
        __syncthreads();
        int gid = blockIdx.x * 256 + tid;         // n*16 + b
        const float2* hp = (const float2*)(g_h + gid * 6);
        float2 h01 = hp[0], h23 = hp[1], h45 = hp[2];
        float h6[6] = {h01.x, h01.y, h23.x, h23.y, h45.x, h45.y};
        float hn8[8];
#pragma unroll
        for (int k = 0; k < 8; k++) {
            float s = 0.f;
#pragma unroll
            for (int d = 0; d < 6; d++) s += h6[d] * sgw[d * 8 + k];
            hn8[k] = s;
        }
        float4* hnp = (float4*)(g_hn + gid * 8);
        hnp[0] = make_float4(hn8[0], hn8[1], hn8[2], hn8[3]);
        hnp[1] = make_float4(hn8[4], hn8[5], hn8[6], hn8[7]);
        float2 si, sj;
        si.x = hn8[0]*satt[0] + hn8[1]*satt[1] + hn8[2]*satt[2] + hn8[3]*satt[3];
        sj.x = hn8[0]*satt[4] + hn8[1]*satt[5] + hn8[2]*satt[6] + hn8[3]*satt[7];
        si.y = hn8[4]*satt[8] + hn8[5]*satt[9] + hn8[6]*satt[10] + hn8[7]*satt[11];
        sj.y = hn8[4]*satt[12] + hn8[5]*satt[13] + hn8[6]*satt[14] + hn8[7]*satt[15];
        ((float2*)g_si)[gid] = si;
        ((float2*)g_sj)[gid] = sj;
    } else {
        int ok = (ei[2 * tid + 1] == 0);
        int ef = __syncthreads_and(ok);
        int e = (blockIdx.x - 256) * 256 + tid;
        int dst = ef ? ei[2 * (E_EDGES + e)] : ei[E_EDGES + e];
        int src = ef ? ei[2 * e] : ei[e];
        int pos = atomicAdd(&g_cur[dst], 1);
        g_csr[pos] = src;
    }
}

// ---------------- L4 (PROFILED): warp-per-destination softmax + aggregate ----------------
// blocks [0,512): 8 warps, warp = 1 dst; lane = b*2+h; acc[4] = c-vector.
// blocks [512,528): zero g_xcat for next run
__global__ __launch_bounds__(256) void k_gat(const float* __restrict__ gbias) {
    int tid = threadIdx.x;
    if (blockIdx.x >= 512) {
        ((float4*)g_xcat)[(blockIdx.x - 512) * 256 + tid] = make_float4(0.f, 0.f, 0.f, 0.f);
        return;
    }
    int wid = tid >> 5, lane = tid & 31;
    int n = blockIdx.x * 8 + wid;
    int base = g_off[n], deg = g_off[n + 1] - base;
    float si = g_si[n * 32 + lane];
    float b0c = gbias[0], b1c = gbias[1], b2c = gbias[2], b3c = gbias[3];

    float wsum = 0.f;
    float a0 = 0.f, a1 = 0.f, a2 = 0.f, a3 = 0.f;
    for (int e0 = 0; e0 < deg; e0 += 32) {
        int myidx = (e0 + lane < deg) ? g_csr[base + e0 + lane] : 0;
        int m = min(32, deg - e0);
        for (int j = 0; j < m; j++) {
            int s = __shfl_sync(0xffffffffu, myidx, j);
            float a = si + g_sj[s * 32 + lane];
            a = a >= 0.f ? a : 0.2f * a;
            a = fminf(fmaxf(a, -30.f), 30.f);    // tripwire only; scores are O(1)
            float w = __expf(a);
            wsum += w;
            float4 hv = *(const float4*)(g_hn + s * 128 + lane * 4);
            a0 += w * hv.x; a1 += w * hv.y; a2 += w * hv.z; a3 += w * hv.w;
        }
    }
    float inv = (wsum > 0.f) ? 1.f / (wsum * (float)deg) : 0.f;
    a0 *= inv; a1 *= inv; a2 *= inv; a3 *= inv;
    // head mean: lanes (b*2) and (b*2+1) hold h=0,1
    float v0 = 0.5f * (a0 + __shfl_xor_sync(0xffffffffu, a0, 1)) + b0c;
    float v1 = 0.5f * (a1 + __shfl_xor_sync(0xffffffffu, a1, 1)) + b1c;
    float v2 = 0.5f * (a2 + __shfl_xor_sync(0xffffffffu, a2, 1)) + b2c;
    float v3 = 0.5f * (a3 + __shfl_xor_sync(0xffffffffu, a3, 1)) + b3c;
    if ((lane & 1) == 0) {
        int b = lane >> 1;
        float* op = g_o + b * 16384 + n;
        op[0]     = lrelu(v0, 0.01f);
        op[4096]  = lrelu(v1, 0.01f);
        op[8192]  = lrelu(v2, 0.01f);
        op[12288] = lrelu(v3, 0.01f);
    }
}

// ---------------- L5: readout ----------------
__global__ __launch_bounds__(256) void k_readout(const float* __restrict__ ow, float* __restrict__ out) {
    int k = blockIdx.x, sl = blockIdx.y;
    int tid = threadIdx.x;
    float acc[16];
#pragma unroll
    for (int b = 0; b < 16; b++) acc[b] = 0.f;
    const float* wk = ow + k * 16384 + sl * 4096;
    const float* op = g_o + sl * 4096;
    for (int it = 0; it < 16; it++) {
        int i = tid + it * 256;
        float w = wk[i];
#pragma unroll
        for (int b = 0; b < 16; b++) acc[b] += w * op[b * 16384 + i];
    }
    __shared__ float red[8][16];
    int lane = tid & 31, wid = tid >> 5;
#pragma unroll
    for (int b = 0; b < 16; b++) {
        float v = acc[b];
#pragma unroll
        for (int o = 16; o; o >>= 1) v += __shfl_xor_sync(0xffffffffu, v, o);
        if (lane == 0) red[wid][b] = v;
    }
    __syncthreads();
    if (tid < 16) {
        float s = 0.f;
#pragma unroll
        for (int w = 0; w < 8; w++) s += red[w][tid];
        atomicAdd(&out[tid * 32 + k], s);
    }
}

// ---------------- launch ----------------
extern "C" void kernel_launch(void* const* d_in, const int* in_sizes, int n_in,
                              void* d_out, int out_size) {
    const float* x    = (const float*)d_in[0];
    const int*   ei   = (const int*)  d_in[1];
    const float* Wsub = (const float*)d_in[2];
    const float* bsub = (const float*)d_in[3];
    const float* fw   = (const float*)d_in[4];
    const float* mr   = (const float*)d_in[5];
    const float* fb   = (const float*)d_in[6];
    const float* gw   = (const float*)d_in[7];
    const float* gatt = (const float*)d_in[8];
    const float* gb   = (const float*)d_in[9];
    const float* ow   = (const float*)d_in[10];
    const float* ob   = (const float*)d_in[11];
    float* out = (float*)d_out;

    k_main1<<<2624, 256>>>(x, Wsub, fw, mr, ei);   // 1: subnet + prep + hist (overlapped)
    k_fcs2<<<2049, 256>>>(fw, fb, bsub, out, ob);  // 2: packed FC + scan
    k_mid<<<512, 256>>>(gw, gatt, ei);             // 3: proj + scatter
    k_gat<<<528, 256>>>(gb);                       // 4: <- profiled (warp-per-dst GAT + zero)
    k_readout<<<dim3(32, 4), 256>>>(ow, out);      // 5
}

// round 11
// speedup vs baseline: 1.4065x; 1.0188x over previous
#include <cuda_runtime.h>

#define E_EDGES 65536
#define NGO 4096
#define B_SZ 16
#define G_SZ 1024

// ---------------- scratch (__device__ globals; no allocs allowed) ----------------
__device__ float g_xcat[B_SZ * G_SZ];        // [B][G] partial sums; zeroed by k_gat for next run
__device__ float g_h[NGO * 96];              // [N][B][6]
__device__ float g_hn[NGO * 128];            // [N][B][2][4]
__device__ float g_si[NGO * 32];             // [N][B][2]
__device__ float g_sj[NGO * 32];             // [N][B][2]
__device__ float g_o[B_SZ * 16384];          // [B][C*N]  (lrelu applied)
__device__ float g_wpk[NGO * 6 * 128];       // packed masked weights [grp][6][128]
__device__ int   g_idxcnt[NGO];              // nnz count per mask group
__device__ int   g_idxbuf[NGO * 1024];       // nnz gene indices per mask group
__device__ int   g_cnt[NGO];                 // zero-init; scan role re-zeroes each run
__device__ int   g_off[NGO + 1];
__device__ int   g_cur[NGO];
__device__ int   g_csr[E_EDGES];             // src per CSR slot

__device__ __forceinline__ float lrelu(float x, float s) { return x >= 0.f ? x : s * x; }

// ---------------- L1: mega-kernel — subnet + mask-compact/weight-pack + histogram ----
// blocks [0,2048): subnet; [2048,2560): prep (compact + pack); [2560,2624): hist
__global__ __launch_bounds__(256) void k_main1(const float* __restrict__ x,
                                               const float* __restrict__ Wsub,
                                               const float* __restrict__ fw,
                                               const float* __restrict__ mr,
                                               const int* __restrict__ ei) {
    int bid = blockIdx.x, tid = threadIdx.x;
    if (bid < 2048) {
        // ---- subnet: 4 genes x 64 t-rows x 8 b per block ----
        int bx = bid & 255, by = (bid >> 8) & 3, bz = bid >> 10;
        int g0 = bx * 4;
        int c = tid & 15, tr = tid >> 4;
        int gene = g0 + (c >> 2), pq = c & 3;
        int b0 = bz * 8;
        const float4* x4 = (const float4*)x;
        const float4* w4 = (const float4*)Wsub;
        float acc[8];
#pragma unroll
        for (int b = 0; b < 8; b++) acc[b] = 0.f;
        int tbase = by * 64;
#pragma unroll 1
        for (int pass = 0; pass < 4; pass++) {
            int t = tbase + pass * 16 + tr;
            float4 w = w4[gene * 1024 + t * 4 + pq];
            int xoff = t * 4096 + g0 * 4 + c;
#pragma unroll
            for (int b = 0; b < 8; b++) {
                float4 xv = x4[(b0 + b) * 1048576 + xoff];
                acc[b] += w.x * xv.x + w.y * xv.y + w.z * xv.z + w.w * xv.w;
            }
        }
        __shared__ float red[8][4][8];
        int lane = tid & 31, wid = tid >> 5;
#pragma unroll
        for (int b = 0; b < 8; b++) {
            float v = acc[b];
            v += __shfl_xor_sync(0xffffffffu, v, 16);
            v += __shfl_xor_sync(0xffffffffu, v, 2);
            v += __shfl_xor_sync(0xffffffffu, v, 1);
            if ((lane & 3) == 0 && lane < 16) red[wid][lane >> 2][b] = v;
        }
        __syncthreads();
        if (tid < 32) {
            int gl = tid >> 3, b = tid & 7;
            float s = 0.f;
#pragma unroll
            for (int w2 = 0; w2 < 8; w2++) s += red[w2][gl][b];
            atomicAdd(&g_xcat[(b0 + b) * G_SZ + g0 + gl], s);
        }
    } else if (bid < 2560) {
        // ---- prep: warp per group — compact mask row, pack 6 weight rows ----
        __shared__ int s_idx[8][128];
        int w = tid >> 5, lane = tid & 31;
        int grp = (bid - 2048) * 8 + w;
        const float* row = mr + (size_t)grp * 6144;   // rows 6g..6g+5 identical
        int* gout = g_idxbuf + grp * 1024;
        int cnt = 0;
#pragma unroll 4
        for (int c = 0; c < 32; c++) {
            float v = row[c * 32 + lane];
            unsigned ball = __ballot_sync(0xffffffffu, v != 0.f);
            if (v != 0.f) {
                int p = cnt + __popc(ball & ((1u << lane) - 1u));
                gout[p] = c * 32 + lane;
                if (p < 128) s_idx[w][p] = c * 32 + lane;
            }
            cnt += __popc(ball);
        }
        if (lane == 0) g_idxcnt[grp] = cnt;
        __syncwarp();
        const float* wb = fw + (size_t)grp * 6144;
        float* pk = g_wpk + grp * 768;
        int cend = min(cnt, 128);
        for (int k = lane; k < cend; k += 32) {
            int g = s_idx[w][k];
#pragma unroll
            for (int r = 0; r < 6; r++) pk[r * 128 + k] = wb[r * 1024 + g];
        }
    } else {
        // ---- hist: local int64/int32 detect + dst histogram ----
        int ok = (ei[2 * tid + 1] == 0);
        int ef = __syncthreads_and(ok);
        int e0 = (bid - 2560) * 1024;
#pragma unroll
        for (int it = 0; it < 4; it++) {
            int e = e0 + it * 256 + tid;
            int dst = ef ? ei[2 * (E_EDGES + e)] : ei[E_EDGES + e];
            atomicAdd(&g_cnt[dst], 1);
        }
    }
}

// ---------------- L2: packed-sparse FC (+ scan role) ----------------
__global__ __launch_bounds__(256) void k_fcs2(const float* __restrict__ fw,
                                              const float* __restrict__ fb,
                                              const float* __restrict__ bsub,
                                              float* __restrict__ out,
                                              const float* __restrict__ ob) {
    int tid = threadIdx.x;
    if (blockIdx.x < 2048) {
        int wid = tid >> 5, lane = tid & 31;
        int grp = blockIdx.x * 2 + (wid >> 2);
        int b0 = (wid & 3) * 4;
        int cnt = g_idxcnt[grp];
        const int* idx = g_idxbuf + grp * 1024;
        const float* pk = g_wpk + grp * 768;
        const float* wb = fw + (size_t)grp * 6144;
        float acc[6][4];
#pragma unroll
        for (int r = 0; r < 6; r++)
#pragma unroll
            for (int b = 0; b < 4; b++) acc[r][b] = 0.f;
        int cend = min(cnt, 128);
        for (int k = lane; k < cend; k += 32) {
            int g = idx[k];
            float bs = bsub[g];
            float xv[4];
#pragma unroll
            for (int b = 0; b < 4; b++) xv[b] = lrelu(g_xcat[(b0 + b) * G_SZ + g] + bs, 0.01f);
#pragma unroll
            for (int r = 0; r < 6; r++) {
                float wv = pk[r * 128 + k];
#pragma unroll
                for (int b = 0; b < 4; b++) acc[r][b] += wv * xv[b];
            }
        }
        if (cnt > 128) {                         // paranoia path; statistically never taken
            for (int k = 128 + lane; k < cnt; k += 32) {
                int g = idx[k];
                float bs = bsub[g];
                float xv[4];
#pragma unroll
                for (int b = 0; b < 4; b++) xv[b] = lrelu(g_xcat[(b0 + b) * G_SZ + g] + bs, 0.01f);
#pragma unroll
                for (int r = 0; r < 6; r++) {
                    float wv = wb[r * 1024 + g];
#pragma unroll
                    for (int b = 0; b < 4; b++) acc[r][b] += wv * xv[b];
                }
            }
        }
#pragma unroll
        for (int r = 0; r < 6; r++) {
#pragma unroll
            for (int b = 0; b < 4; b++) {
                float v = acc[r][b];
#pragma unroll
                for (int o = 16; o; o >>= 1) v += __shfl_xor_sync(0xffffffffu, v, o);
                if (lane == 0) {
                    int j = grp * 6 + r;
                    int d = j >> 12, n = j & 4095;
                    g_h[n * 96 + (b0 + b) * 6 + d] = lrelu(v + fb[j], 0.01f);
                }
            }
        }
    } else {
        // ---- scan role ----
        int lane = tid & 31, wid = tid >> 5;
        int base = tid * 16;
        int c[16];
        const int4* cp = (const int4*)&g_cnt[base];
#pragma unroll
        for (int q = 0; q < 4; q++) {
            int4 v = cp[q];
            c[q * 4 + 0] = v.x; c[q * 4 + 1] = v.y; c[q * 4 + 2] = v.z; c[q * 4 + 3] = v.w;
        }
        int loc[16], s = 0;
#pragma unroll
        for (int i = 0; i < 16; i++) { loc[i] = s; s += c[i]; }
        int v = s;
#pragma unroll
        for (int d = 1; d < 32; d <<= 1) {
            int o = __shfl_up_sync(0xffffffffu, v, d);
            if (lane >= d) v += o;
        }
        __shared__ int wsum[8];
        if (lane == 31) wsum[wid] = v;
        __syncthreads();
        int wbase = 0;
#pragma unroll
        for (int w = 0; w < 8; w++) wbase += (w < wid) ? wsum[w] : 0;
        int excl = wbase + v - s;
#pragma unroll
        for (int i = 0; i < 16; i++) {
            int e = excl + loc[i];
            g_off[base + i] = e;
            g_cur[base + i] = e;
            g_cnt[base + i] = 0;
        }
        if (tid == 255) g_off[NGO] = excl + s;
        for (int i = tid; i < 512; i += 256) out[i] = ob[i & 31];
    }
}

// ---------------- L3: fused GAT projection + CSR scatter ----------------
__global__ void k_mid(const float* __restrict__ gw, const float* __restrict__ gatt,
                      const int* __restrict__ ei) {
    int tid = threadIdx.x;
    if (blockIdx.x < 256) {
        __shared__ float sgw[48], satt[16];
        if (tid < 48) sgw[tid] = gw[tid];
        if (tid < 16) satt[tid] = gatt[tid];
        __syncthreads();
        int gid = blockIdx.x * 256 + tid;         // n*16 + b
        const float2* hp = (const float2*)(g_h + gid * 6);
        float2 h01 = hp[0], h23 = hp[1], h45 = hp[2];
        float h6[6] = {h01.x, h01.y, h23.x, h23.y, h45.x, h45.y};
        float hn8[8];
#pragma unroll
        for (int k = 0; k < 8; k++) {
            float s = 0.f;
#pragma unroll
            for (int d = 0; d < 6; d++) s += h6[d] * sgw[d * 8 + k];
            hn8[k] = s;
        }
        float4* hnp = (float4*)(g_hn + gid * 8);
        hnp[0] = make_float4(hn8[0], hn8[1], hn8[2], hn8[3]);
        hnp[1] = make_float4(hn8[4], hn8[5], hn8[6], hn8[7]);
        float2 si, sj;
        si.x = hn8[0]*satt[0] + hn8[1]*satt[1] + hn8[2]*satt[2] + hn8[3]*satt[3];
        sj.x = hn8[0]*satt[4] + hn8[1]*satt[5] + hn8[2]*satt[6] + hn8[3]*satt[7];
        si.y = hn8[4]*satt[8] + hn8[5]*satt[9] + hn8[6]*satt[10] + hn8[7]*satt[11];
        sj.y = hn8[4]*satt[12] + hn8[5]*satt[13] + hn8[6]*satt[14] + hn8[7]*satt[15];
        ((float2*)g_si)[gid] = si;
        ((float2*)g_sj)[gid] = sj;
    } else {
        int ok = (ei[2 * tid + 1] == 0);
        int ef = __syncthreads_and(ok);
        int e = (blockIdx.x - 256) * 256 + tid;
        int dst = ef ? ei[2 * (E_EDGES + e)] : ei[E_EDGES + e];
        int src = ef ? ei[2 * e] : ei[e];
        int pos = atomicAdd(&g_cur[dst], 1);
        g_csr[pos] = src;
    }
}

// ---------------- L4 (PROFILED): warp-per-destination GAT, edge loop unrolled x4 ----
// blocks [0,512): 8 warps, warp = 1 dst; lane = b*2+h; acc[4] = c-vector.
// blocks [512,528): zero g_xcat for next run
__global__ __launch_bounds__(256) void k_gat(const float* __restrict__ gbias) {
    int tid = threadIdx.x;
    if (blockIdx.x >= 512) {
        ((float4*)g_xcat)[(blockIdx.x - 512) * 256 + tid] = make_float4(0.f, 0.f, 0.f, 0.f);
        return;
    }
    int wid = tid >> 5, lane = tid & 31;
    int n = blockIdx.x * 8 + wid;
    int base = g_off[n], deg = g_off[n + 1] - base;
    float si = g_si[n * 32 + lane];
    float b0c = gbias[0], b1c = gbias[1], b2c = gbias[2], b3c = gbias[3];

    float wsum = 0.f;
    float a0 = 0.f, a1 = 0.f, a2 = 0.f, a3 = 0.f;
    for (int e0 = 0; e0 < deg; e0 += 32) {
        int myidx = (e0 + lane < deg) ? g_csr[base + e0 + lane] : 0;
        int m = min(32, deg - e0);
        int j = 0;
        for (; j + 3 < m; j += 4) {
            int s0 = __shfl_sync(0xffffffffu, myidx, j);
            int s1 = __shfl_sync(0xffffffffu, myidx, j + 1);
            int s2 = __shfl_sync(0xffffffffu, myidx, j + 2);
            int s3 = __shfl_sync(0xffffffffu, myidx, j + 3);
            float t0 = g_sj[s0 * 32 + lane];
            float t1 = g_sj[s1 * 32 + lane];
            float t2 = g_sj[s2 * 32 + lane];
            float t3 = g_sj[s3 * 32 + lane];
            float4 h0 = *(const float4*)(g_hn + s0 * 128 + lane * 4);
            float4 h1 = *(const float4*)(g_hn + s1 * 128 + lane * 4);
            float4 h2 = *(const float4*)(g_hn + s2 * 128 + lane * 4);
            float4 h3 = *(const float4*)(g_hn + s3 * 128 + lane * 4);
            float q0 = si + t0, q1 = si + t1, q2 = si + t2, q3 = si + t3;
            q0 = q0 >= 0.f ? q0 : 0.2f * q0;  q1 = q1 >= 0.f ? q1 : 0.2f * q1;
            q2 = q2 >= 0.f ? q2 : 0.2f * q2;  q3 = q3 >= 0.f ? q3 : 0.2f * q3;
            q0 = fminf(fmaxf(q0, -30.f), 30.f); q1 = fminf(fmaxf(q1, -30.f), 30.f);
            q2 = fminf(fmaxf(q2, -30.f), 30.f); q3 = fminf(fmaxf(q3, -30.f), 30.f);
            float w0 = __expf(q0), w1 = __expf(q1), w2 = __expf(q2), w3 = __expf(q3);
            wsum += (w0 + w1) + (w2 + w3);
            a0 += w0 * h0.x + w1 * h1.x + w2 * h2.x + w3 * h3.x;
            a1 += w0 * h0.y + w1 * h1.y + w2 * h2.y + w3 * h3.y;
            a2 += w0 * h0.z + w1 * h1.z + w2 * h2.z + w3 * h3.z;
            a3 += w0 * h0.w + w1 * h1.w + w2 * h2.w + w3 * h3.w;
        }
        for (; j < m; j++) {
            int s = __shfl_sync(0xffffffffu, myidx, j);
            float a = si + g_sj[s * 32 + lane];
            a = a >= 0.f ? a : 0.2f * a;
            a = fminf(fmaxf(a, -30.f), 30.f);
            float w = __expf(a);
            wsum += w;
            float4 hv = *(const float4*)(g_hn + s * 128 + lane * 4);
            a0 += w * hv.x; a1 += w * hv.y; a2 += w * hv.z; a3 += w * hv.w;
        }
    }
    float inv = (wsum > 0.f) ? 1.f / (wsum * (float)deg) : 0.f;
    a0 *= inv; a1 *= inv; a2 *= inv; a3 *= inv;
    // head mean: lanes (b*2) and (b*2+1) hold h=0,1
    float v0 = 0.5f * (a0 + __shfl_xor_sync(0xffffffffu, a0, 1)) + b0c;
    float v1 = 0.5f * (a1 + __shfl_xor_sync(0xffffffffu, a1, 1)) + b1c;
    float v2 = 0.5f * (a2 + __shfl_xor_sync(0xffffffffu, a2, 1)) + b2c;
    float v3 = 0.5f * (a3 + __shfl_xor_sync(0xffffffffu, a3, 1)) + b3c;
    if ((lane & 1) == 0) {
        int b = lane >> 1;
        float* op = g_o + b * 16384 + n;
        op[0]     = lrelu(v0, 0.01f);
        op[4096]  = lrelu(v1, 0.01f);
        op[8192]  = lrelu(v2, 0.01f);
        op[12288] = lrelu(v3, 0.01f);
    }
}

// ---------------- L5: readout ----------------
__global__ __launch_bounds__(256) void k_readout(const float* __restrict__ ow, float* __restrict__ out) {
    int k = blockIdx.x, sl = blockIdx.y;
    int tid = threadIdx.x;
    float acc[16];
#pragma unroll
    for (int b = 0; b < 16; b++) acc[b] = 0.f;
    const float* wk = ow + k * 16384 + sl * 4096;
    const float* op = g_o + sl * 4096;
    for (int it = 0; it < 16; it++) {
        int i = tid + it * 256;
        float w = wk[i];
#pragma unroll
        for (int b = 0; b < 16; b++) acc[b] += w * op[b * 16384 + i];
    }
    __shared__ float red[8][16];
    int lane = tid & 31, wid = tid >> 5;
#pragma unroll
    for (int b = 0; b < 16; b++) {
        float v = acc[b];
#pragma unroll
        for (int o = 16; o; o >>= 1) v += __shfl_xor_sync(0xffffffffu, v, o);
        if (lane == 0) red[wid][b] = v;
    }
    __syncthreads();
    if (tid < 16) {
        float s = 0.f;
#pragma unroll
        for (int w = 0; w < 8; w++) s += red[w][tid];
        atomicAdd(&out[tid * 32 + k], s);
    }
}

// ---------------- launch ----------------
extern "C" void kernel_launch(void* const* d_in, const int* in_sizes, int n_in,
                              void* d_out, int out_size) {
    const float* x    = (const float*)d_in[0];
    const int*   ei   = (const int*)  d_in[1];
    const float* Wsub = (const float*)d_in[2];
    const float* bsub = (const float*)d_in[3];
    const float* fw   = (const float*)d_in[4];
    const float* mr   = (const float*)d_in[5];
    const float* fb   = (const float*)d_in[6];
    const float* gw   = (const float*)d_in[7];
    const float* gatt = (const float*)d_in[8];
    const float* gb   = (const float*)d_in[9];
    const float* ow   = (const float*)d_in[10];
    const float* ob   = (const float*)d_in[11];
    float* out = (float*)d_out;

    k_main1<<<2624, 256>>>(x, Wsub, fw, mr, ei);   // 1: subnet + prep + hist (overlapped)
    k_fcs2<<<2049, 256>>>(fw, fb, bsub, out, ob);  // 2: packed FC + scan
    k_mid<<<512, 256>>>(gw, gatt, ei);             // 3: proj + scatter
    k_gat<<<528, 256>>>(gb);                       // 4: <- profiled (unrolled GAT + zero)
    k_readout<<<dim3(32, 4), 256>>>(ow, out);      // 5
}

// round 12
// speedup vs baseline: 1.4768x; 1.0500x over previous
#include <cuda_runtime.h>

#define E_EDGES 65536
#define NGO 4096
#define B_SZ 16
#define G_SZ 1024
#define BKT_CAP 96

// ---------------- scratch (__device__ globals; no allocs allowed) ----------------
__device__ float g_xcat[B_SZ * G_SZ];        // [B][G] partial sums; zeroed by k_gat for next run
__device__ float g_h[NGO * 96];              // [N][B][6]
__device__ float g_hn[NGO * 128];            // [N][B][2][4]
__device__ float g_si[NGO * 32];             // [N][B][2]
__device__ float g_sj[NGO * 32];             // [N][B][2]
__device__ float g_o[B_SZ * 16384];          // [B][C*N]  (lrelu applied)
__device__ float g_wpk[NGO * 6 * 128];       // packed masked weights [grp][6][128]
__device__ int   g_idxcnt[NGO];              // nnz count per mask group
__device__ int   g_idxbuf[NGO * 1024];       // nnz gene indices per mask group
__device__ int   g_cnt[NGO];                 // zero-init; k_readout role re-zeroes each run
__device__ int   g_bkt[NGO * BKT_CAP];       // direct CSR buckets: src per slot

__device__ __forceinline__ float lrelu(float x, float s) { return x >= 0.f ? x : s * x; }

// ---------------- L1: mega-kernel — subnet + mask-compact/weight-pack + edge-bucket ----
// blocks [0,2048): subnet; [2048,2560): prep (compact + pack); [2560,2624): edge bucket
__global__ __launch_bounds__(256) void k_main1(const float* __restrict__ x,
                                               const float* __restrict__ Wsub,
                                               const float* __restrict__ fw,
                                               const float* __restrict__ mr,
                                               const int* __restrict__ ei) {
    int bid = blockIdx.x, tid = threadIdx.x;
    if (bid < 2048) {
        // ---- subnet: 4 genes x 64 t-rows x 8 b per block ----
        int bx = bid & 255, by = (bid >> 8) & 3, bz = bid >> 10;
        int g0 = bx * 4;
        int c = tid & 15, tr = tid >> 4;
        int gene = g0 + (c >> 2), pq = c & 3;
        int b0 = bz * 8;
        const float4* x4 = (const float4*)x;
        const float4* w4 = (const float4*)Wsub;
        float acc[8];
#pragma unroll
        for (int b = 0; b < 8; b++) acc[b] = 0.f;
        int tbase = by * 64;
#pragma unroll 1
        for (int pass = 0; pass < 4; pass++) {
            int t = tbase + pass * 16 + tr;
            float4 w = w4[gene * 1024 + t * 4 + pq];
            int xoff = t * 4096 + g0 * 4 + c;
#pragma unroll
            for (int b = 0; b < 8; b++) {
                float4 xv = x4[(b0 + b) * 1048576 + xoff];
                acc[b] += w.x * xv.x + w.y * xv.y + w.z * xv.z + w.w * xv.w;
            }
        }
        __shared__ float red[8][4][8];
        int lane = tid & 31, wid = tid >> 5;
#pragma unroll
        for (int b = 0; b < 8; b++) {
            float v = acc[b];
            v += __shfl_xor_sync(0xffffffffu, v, 16);
            v += __shfl_xor_sync(0xffffffffu, v, 2);
            v += __shfl_xor_sync(0xffffffffu, v, 1);
            if ((lane & 3) == 0 && lane < 16) red[wid][lane >> 2][b] = v;
        }
        __syncthreads();
        if (tid < 32) {
            int gl = tid >> 3, b = tid & 7;
            float s = 0.f;
#pragma unroll
            for (int w2 = 0; w2 < 8; w2++) s += red[w2][gl][b];
            atomicAdd(&g_xcat[(b0 + b) * G_SZ + g0 + gl], s);
        }
    } else if (bid < 2560) {
        // ---- prep: warp per group — compact mask row, pack 6 weight rows ----
        __shared__ int s_idx[8][128];
        int w = tid >> 5, lane = tid & 31;
        int grp = (bid - 2048) * 8 + w;
        const float* row = mr + (size_t)grp * 6144;   // rows 6g..6g+5 identical
        int* gout = g_idxbuf + grp * 1024;
        int cnt = 0;
#pragma unroll 4
        for (int c = 0; c < 32; c++) {
            float v = row[c * 32 + lane];
            unsigned ball = __ballot_sync(0xffffffffu, v != 0.f);
            if (v != 0.f) {
                int p = cnt + __popc(ball & ((1u << lane) - 1u));
                gout[p] = c * 32 + lane;
                if (p < 128) s_idx[w][p] = c * 32 + lane;
            }
            cnt += __popc(ball);
        }
        if (lane == 0) g_idxcnt[grp] = cnt;
        __syncwarp();
        const float* wb = fw + (size_t)grp * 6144;
        float* pk = g_wpk + grp * 768;
        int cend = min(cnt, 128);
        for (int k = lane; k < cend; k += 32) {
            int g = s_idx[w][k];
#pragma unroll
            for (int r = 0; r < 6; r++) pk[r * 128 + k] = wb[r * 1024 + g];
        }
    } else {
        // ---- edge bucket: local int64/int32 detect + direct CSR build ----
        int ok = (ei[2 * tid + 1] == 0);
        int ef = __syncthreads_and(ok);
        int e0 = (bid - 2560) * 1024;
#pragma unroll
        for (int it = 0; it < 4; it++) {
            int e = e0 + it * 256 + tid;
            int dst = ef ? ei[2 * (E_EDGES + e)] : ei[E_EDGES + e];
            int src = ef ? ei[2 * e] : ei[e];
            int pos = atomicAdd(&g_cnt[dst], 1);
            if (pos < BKT_CAP) g_bkt[dst * BKT_CAP + pos] = src;  // P(overflow) ~ 1e-40
        }
    }
}

// ---------------- L2: packed-sparse FC (+ out bias init role) ----------------
__global__ __launch_bounds__(256) void k_fcs2(const float* __restrict__ fw,
                                              const float* __restrict__ fb,
                                              const float* __restrict__ bsub,
                                              float* __restrict__ out,
                                              const float* __restrict__ ob) {
    int tid = threadIdx.x;
    if (blockIdx.x < 2048) {
        int wid = tid >> 5, lane = tid & 31;
        int grp = blockIdx.x * 2 + (wid >> 2);
        int b0 = (wid & 3) * 4;
        int cnt = g_idxcnt[grp];
        const int* idx = g_idxbuf + grp * 1024;
        const float* pk = g_wpk + grp * 768;
        const float* wb = fw + (size_t)grp * 6144;
        float acc[6][4];
#pragma unroll
        for (int r = 0; r < 6; r++)
#pragma unroll
            for (int b = 0; b < 4; b++) acc[r][b] = 0.f;
        int cend = min(cnt, 128);
        for (int k = lane; k < cend; k += 32) {
            int g = idx[k];
            float bs = bsub[g];
            float xv[4];
#pragma unroll
            for (int b = 0; b < 4; b++) xv[b] = lrelu(g_xcat[(b0 + b) * G_SZ + g] + bs, 0.01f);
#pragma unroll
            for (int r = 0; r < 6; r++) {
                float wv = pk[r * 128 + k];
#pragma unroll
                for (int b = 0; b < 4; b++) acc[r][b] += wv * xv[b];
            }
        }
        if (cnt > 128) {                         // paranoia path; statistically never taken
            for (int k = 128 + lane; k < cnt; k += 32) {
                int g = idx[k];
                float bs = bsub[g];
                float xv[4];
#pragma unroll
                for (int b = 0; b < 4; b++) xv[b] = lrelu(g_xcat[(b0 + b) * G_SZ + g] + bs, 0.01f);
#pragma unroll
                for (int r = 0; r < 6; r++) {
                    float wv = wb[r * 1024 + g];
#pragma unroll
                    for (int b = 0; b < 4; b++) acc[r][b] += wv * xv[b];
                }
            }
        }
#pragma unroll
        for (int r = 0; r < 6; r++) {
#pragma unroll
            for (int b = 0; b < 4; b++) {
                float v = acc[r][b];
#pragma unroll
                for (int o = 16; o; o >>= 1) v += __shfl_xor_sync(0xffffffffu, v, o);
                if (lane == 0) {
                    int j = grp * 6 + r;
                    int d = j >> 12, n = j & 4095;
                    g_h[n * 96 + (b0 + b) * 6 + d] = lrelu(v + fb[j], 0.01f);
                }
            }
        }
    } else {
        for (int i = tid; i < 512; i += 256) out[i] = ob[i & 31];
    }
}

// ---------------- L3: GAT projection ----------------
__global__ void k_mid(const float* __restrict__ gw, const float* __restrict__ gatt) {
    int tid = threadIdx.x;
    __shared__ float sgw[48], satt[16];
    if (tid < 48) sgw[tid] = gw[tid];
    if (tid < 16) satt[tid] = gatt[tid];
    __syncthreads();
    int gid = blockIdx.x * 256 + tid;             // n*16 + b
    const float2* hp = (const float2*)(g_h + gid * 6);
    float2 h01 = hp[0], h23 = hp[1], h45 = hp[2];
    float h6[6] = {h01.x, h01.y, h23.x, h23.y, h45.x, h45.y};
    float hn8[8];
#pragma unroll
    for (int k = 0; k < 8; k++) {
        float s = 0.f;
#pragma unroll
        for (int d = 0; d < 6; d++) s += h6[d] * sgw[d * 8 + k];
        hn8[k] = s;
    }
    float4* hnp = (float4*)(g_hn + gid * 8);
    hnp[0] = make_float4(hn8[0], hn8[1], hn8[2], hn8[3]);
    hnp[1] = make_float4(hn8[4], hn8[5], hn8[6], hn8[7]);
    float2 si, sj;
    si.x = hn8[0]*satt[0] + hn8[1]*satt[1] + hn8[2]*satt[2] + hn8[3]*satt[3];
    sj.x = hn8[0]*satt[4] + hn8[1]*satt[5] + hn8[2]*satt[6] + hn8[3]*satt[7];
    si.y = hn8[4]*satt[8] + hn8[5]*satt[9] + hn8[6]*satt[10] + hn8[7]*satt[11];
    sj.y = hn8[4]*satt[12] + hn8[5]*satt[13] + hn8[6]*satt[14] + hn8[7]*satt[15];
    ((float2*)g_si)[gid] = si;
    ((float2*)g_sj)[gid] = sj;
}

// ---------------- L4 (PROFILED): warp-per-destination GAT, unroll x8 ----------------
// blocks [0,512): 8 warps, warp = 1 dst; lane = b*2+h; acc[4] = c-vector.
// blocks [512,528): zero g_xcat for next run
__global__ __launch_bounds__(256) void k_gat(const float* __restrict__ gbias) {
    int tid = threadIdx.x;
    if (blockIdx.x >= 512) {
        ((float4*)g_xcat)[(blockIdx.x - 512) * 256 + tid] = make_float4(0.f, 0.f, 0.f, 0.f);
        return;
    }
    int wid = tid >> 5, lane = tid & 31;
    int n = blockIdx.x * 8 + wid;
    int deg = min(g_cnt[n], BKT_CAP);
    const int* bkt = g_bkt + n * BKT_CAP;
    float si = g_si[n * 32 + lane];
    float b0c = gbias[0], b1c = gbias[1], b2c = gbias[2], b3c = gbias[3];

    float wsum = 0.f;
    float a0 = 0.f, a1 = 0.f, a2 = 0.f, a3 = 0.f;
    for (int e0 = 0; e0 < deg; e0 += 32) {
        int myidx = (e0 + lane < deg) ? bkt[e0 + lane] : 0;
        int m = min(32, deg - e0);
        int j = 0;
        for (; j + 7 < m; j += 8) {
            int s[8];
            float t[8];
            float4 h[8];
#pragma unroll
            for (int u = 0; u < 8; u++) s[u] = __shfl_sync(0xffffffffu, myidx, j + u);
#pragma unroll
            for (int u = 0; u < 8; u++) t[u] = g_sj[s[u] * 32 + lane];
#pragma unroll
            for (int u = 0; u < 8; u++) h[u] = *(const float4*)(g_hn + s[u] * 128 + lane * 4);
#pragma unroll
            for (int u = 0; u < 8; u++) {
                float q = si + t[u];
                q = q >= 0.f ? q : 0.2f * q;
                q = fminf(fmaxf(q, -30.f), 30.f);
                float w = __expf(q);
                wsum += w;
                a0 += w * h[u].x; a1 += w * h[u].y; a2 += w * h[u].z; a3 += w * h[u].w;
            }
        }
        for (; j + 3 < m; j += 4) {
            int s[4];
            float t[4];
            float4 h[4];
#pragma unroll
            for (int u = 0; u < 4; u++) s[u] = __shfl_sync(0xffffffffu, myidx, j + u);
#pragma unroll
            for (int u = 0; u < 4; u++) t[u] = g_sj[s[u] * 32 + lane];
#pragma unroll
            for (int u = 0; u < 4; u++) h[u] = *(const float4*)(g_hn + s[u] * 128 + lane * 4);
#pragma unroll
            for (int u = 0; u < 4; u++) {
                float q = si + t[u];
                q = q >= 0.f ? q : 0.2f * q;
                q = fminf(fmaxf(q, -30.f), 30.f);
                float w = __expf(q);
                wsum += w;
                a0 += w * h[u].x; a1 += w * h[u].y; a2 += w * h[u].z; a3 += w * h[u].w;
            }
        }
        for (; j < m; j++) {
            int s = __shfl_sync(0xffffffffu, myidx, j);
            float q = si + g_sj[s * 32 + lane];
            q = q >= 0.f ? q : 0.2f * q;
            q = fminf(fmaxf(q, -30.f), 30.f);
            float w = __expf(q);
            wsum += w;
            float4 hv = *(const float4*)(g_hn + s * 128 + lane * 4);
            a0 += w * hv.x; a1 += w * hv.y; a2 += w * hv.z; a3 += w * hv.w;
        }
    }
    float inv = (wsum > 0.f) ? 1.f / (wsum * (float)deg) : 0.f;
    a0 *= inv; a1 *= inv; a2 *= inv; a3 *= inv;
    // head mean: lanes (b*2) and (b*2+1) hold h=0,1
    float v0 = 0.5f * (a0 + __shfl_xor_sync(0xffffffffu, a0, 1)) + b0c;
    float v1 = 0.5f * (a1 + __shfl_xor_sync(0xffffffffu, a1, 1)) + b1c;
    float v2 = 0.5f * (a2 + __shfl_xor_sync(0xffffffffu, a2, 1)) + b2c;
    float v3 = 0.5f * (a3 + __shfl_xor_sync(0xffffffffu, a3, 1)) + b3c;
    if ((lane & 1) == 0) {
        int b = lane >> 1;
        float* op = g_o + b * 16384 + n;
        op[0]     = lrelu(v0, 0.01f);
        op[4096]  = lrelu(v1, 0.01f);
        op[8192]  = lrelu(v2, 0.01f);
        op[12288] = lrelu(v3, 0.01f);
    }
}

// ---------------- L5: readout (+ g_cnt re-zero role) ----------------
__global__ __launch_bounds__(256) void k_readout(const float* __restrict__ ow, float* __restrict__ out) {
    int k = blockIdx.x, sl = blockIdx.y;
    int tid = threadIdx.x;
    if (k == 32) {                                // zero g_cnt for next replay
        ((int4*)g_cnt)[sl * 256 + tid] = make_int4(0, 0, 0, 0);
        return;
    }
    float acc[16];
#pragma unroll
    for (int b = 0; b < 16; b++) acc[b] = 0.f;
    const float* wk = ow + k * 16384 + sl * 4096;
    const float* op = g_o + sl * 4096;
    for (int it = 0; it < 16; it++) {
        int i = tid + it * 256;
        float w = wk[i];
#pragma unroll
        for (int b = 0; b < 16; b++) acc[b] += w * op[b * 16384 + i];
    }
    __shared__ float red[8][16];
    int lane = tid & 31, wid = tid >> 5;
#pragma unroll
    for (int b = 0; b < 16; b++) {
        float v = acc[b];
#pragma unroll
        for (int o = 16; o; o >>= 1) v += __shfl_xor_sync(0xffffffffu, v, o);
        if (lane == 0) red[wid][b] = v;
    }
    __syncthreads();
    if (tid < 16) {
        float s = 0.f;
#pragma unroll
        for (int w = 0; w < 8; w++) s += red[w][tid];
        atomicAdd(&out[tid * 32 + k], s);
    }
}

// ---------------- launch ----------------
extern "C" void kernel_launch(void* const* d_in, const int* in_sizes, int n_in,
                              void* d_out, int out_size) {
    const float* x    = (const float*)d_in[0];
    const int*   ei   = (const int*)  d_in[1];
    const float* Wsub = (const float*)d_in[2];
    const float* bsub = (const float*)d_in[3];
    const float* fw   = (const float*)d_in[4];
    const float* mr   = (const float*)d_in[5];
    const float* fb   = (const float*)d_in[6];
    const float* gw   = (const float*)d_in[7];
    const float* gatt = (const float*)d_in[8];
    const float* gb   = (const float*)d_in[9];
    const float* ow   = (const float*)d_in[10];
    const float* ob   = (const float*)d_in[11];
    float* out = (float*)d_out;

    k_main1<<<2624, 256>>>(x, Wsub, fw, mr, ei);   // 1: subnet + prep + edge bucket
    k_fcs2<<<2049, 256>>>(fw, fb, bsub, out, ob);  // 2: packed FC + out init
    k_mid<<<256, 256>>>(gw, gatt);                 // 3: proj
    k_gat<<<528, 256>>>(gb);                       // 4: <- profiled (bucket GAT x8 + zero)
    k_readout<<<dim3(33, 4), 256>>>(ow, out);      // 5: readout + cnt zero
}